// round 5
// baseline (speedup 1.0000x reference)
#include <cuda_runtime.h>
#include <cuda_bf16.h>
#include <math.h>

// ---------------------------------------------------------------------------
// CSBrainLLMVQ. fp32 throughout.
//   score[t,k] = 0.5*||cb_k||^2 - inp_b.cb_k - pe2[t].G[k],  G = cb @ inp_w
//   out[t]     = code_out[idx[t]] + outp_b,   code_out = cb @ outp_w.T
// GEMMs: fma.rn.f32x2 with MOV-free inner loops at R3's register budget.
// Numerics bit-identical to R3 (same pairing, k-order, GN expression).
// ---------------------------------------------------------------------------

#define BB   32
#define CHN  19
#define NPP  30
#define PSZ  200
#define RR   570
#define TT   18240
#define DMD  200
#define LLM  4096
#define KCB  4096
#define C25  25
#define W8   8
#define HTOT (BB*C25*RR*W8)
#define PETOT (TT*DMD)
#define NFREQ 101

__device__ float g_bufA[HTOT];
__device__ float g_bufB[HTOT];
__device__ float g_pe[PETOT];
__device__ float g_spec[TT*NFREQ];
__device__ float g_G[KCB*DMD];
__device__ float g_c0[KCB];
__device__ float g_cout[KCB*DMD];
__device__ int   g_idx[TT];
__device__ float g_mean[BB*5];
__device__ float g_rstd[BB*5];

__device__ __forceinline__ float gelu_exact(float v) {
    return 0.5f * v * (1.0f + erff(v * 0.70710678118654752f));
}

#define PACKDUP(dst, a) \
    asm("mov.b64 %0, {%1, %1};" : "=l"(dst) : "r"(__float_as_uint(a)))
#define FMA2(acc, a, b) \
    asm("fma.rn.f32x2 %0, %1, %2, %0;" : "+l"(acc) : "l"(a), "l"(b))
#define UNPK2(lo, hi, v) \
    asm("mov.b64 {%0, %1}, %2;" : "=r"(lo), "=r"(hi) : "l"(v))

// ---------------------------------------------------------------------------
__global__ __launch_bounds__(256) void k_conv1(const float* __restrict__ x,
                                               const float* __restrict__ w,
                                               const float* __restrict__ bias) {
    int br = blockIdx.x;
    int b = br / RR, r = br % RR;
    __shared__ float xs[PSZ];
    __shared__ float ws[C25 * 49];
    __shared__ float bs[C25];
    int t = threadIdx.x;
    if (t < PSZ) xs[t] = x[(size_t)br * PSZ + t];
    for (int i = t; i < C25 * 49; i += 256) ws[i] = w[i];
    if (t < C25) bs[t] = bias[t];
    __syncthreads();
    if (t < 200) {
        int oc = t >> 3, ow = t & 7;
        float acc = bs[oc];
        int base = ow * 25 - 24;
        #pragma unroll 7
        for (int k = 0; k < 49; k++) {
            int p = base + k;
            if (p >= 0 && p < PSZ) acc += xs[p] * ws[oc * 49 + k];
        }
        g_bufA[(((size_t)b * C25 + oc) * RR + r) * W8 + ow] = acc;
    }
}

// ---------------------------------------------------------------------------
__global__ __launch_bounds__(256) void k_gnstats(const float* __restrict__ h) {
    int bg = blockIdx.x;
    int b = bg / 5, g = bg % 5;
    float s1 = 0.f, s2 = 0.f;
    const int per = RR * W8;
    for (int i = threadIdx.x; i < 5 * per; i += 256) {
        int oc = g * 5 + i / per;
        int rw = i % per;
        float v = h[(size_t)(b * C25 + oc) * per + rw];
        s1 += v; s2 += v * v;
    }
    __shared__ float r1[256], r2[256];
    int t = threadIdx.x;
    r1[t] = s1; r2[t] = s2;
    __syncthreads();
    for (int s = 128; s > 0; s >>= 1) {
        if (t < s) { r1[t] += r1[t + s]; r2[t] += r2[t + s]; }
        __syncthreads();
    }
    if (t == 0) {
        float m = r1[0] / 22800.f;
        float var = r2[0] / 22800.f - m * m;
        g_mean[bg] = m;
        g_rstd[bg] = rsqrtf(var + 1e-5f);
    }
}

// ---------------------------------------------------------------------------
__global__ __launch_bounds__(256) void k_conv3x(const float* __restrict__ in,
                                                const float* __restrict__ w,
                                                const float* __restrict__ bias,
                                                const float* __restrict__ gns,
                                                const float* __restrict__ gnb,
                                                float* __restrict__ out) {
    int bi = blockIdx.x;
    int b = bi / 72, rt = bi % 72;
    int r0 = rt * 8;
    int nrows = min(8, RR - r0);
    __shared__ float sIn[C25][8][W8];
    __shared__ float sW[C25 * C25 * 3];
    __shared__ float sB[C25];
    __shared__ float sMean[C25], sRstd[C25], sSc[C25], sBi[C25];
    int t = threadIdx.x;
    for (int i = t; i < C25 * C25 * 3; i += 256) sW[i] = w[i];
    if (t < C25) {
        sB[t] = bias[t];
        int bg = b * 5 + t / 5;
        sMean[t] = g_mean[bg];
        sRstd[t] = g_rstd[bg];
        sSc[t]   = gns[t];
        sBi[t]   = gnb[t];
    }
    for (int i = t; i < C25 * nrows * W8; i += 256) {
        int ic = i / (nrows * W8);
        int lr = (i / W8) % nrows;
        int ww = i & 7;
        sIn[ic][lr][ww] = in[(((size_t)b * C25 + ic) * RR + r0 + lr) * W8 + ww];
    }
    __syncthreads();
    for (int i = t; i < C25 * nrows * W8; i += 256) {
        int ic = i / (nrows * W8);
        int lr = (i / W8) % nrows;
        int ww = i & 7;
        float v = (sIn[ic][lr][ww] - sMean[ic]) * sRstd[ic] * sSc[ic] + sBi[ic];
        sIn[ic][lr][ww] = gelu_exact(v);
    }
    __syncthreads();
    if (t < 200) {
        int oc = t >> 3, ww = t & 7;
        for (int lr = 0; lr < nrows; lr++) {
            float acc = sB[oc];
            #pragma unroll
            for (int ic = 0; ic < C25; ic++) {
                const float* wp = &sW[(oc * C25 + ic) * 3];
                if (ww > 0) acc += sIn[ic][lr][ww - 1] * wp[0];
                acc += sIn[ic][lr][ww] * wp[1];
                if (ww < 7) acc += sIn[ic][lr][ww + 1] * wp[2];
            }
            out[(((size_t)b * C25 + oc) * RR + r0 + lr) * W8 + ww] = acc;
        }
    }
}

// ---------------------------------------------------------------------------
__global__ __launch_bounds__(256) void k_dft(const float* __restrict__ x) {
    __shared__ float xs[2][PSZ], twc[PSZ], tws[PSZ];
    int t = threadIdx.x;
    const float* xp = x + (size_t)blockIdx.x * (2 * PSZ);
    for (int i = t; i < 2 * PSZ; i += 256) ((float*)xs)[i] = xp[i];
    if (t < PSZ) {
        float ang = 6.283185307179586f * (float)t / 200.f;
        twc[t] = cosf(ang);
        tws[t] = sinf(ang);
    }
    __syncthreads();
    if (t < 2 * NFREQ) {
        int tok = t / NFREQ, f = t % NFREQ;
        const float* xv = xs[tok];
        float re = 0.f, im = 0.f;
        int m = 0;
        #pragma unroll 8
        for (int n = 0; n < PSZ; n++) {
            re += xv[n] * twc[m];
            im += xv[n] * tws[m];
            m += f;
            if (m >= PSZ) m -= PSZ;
        }
        g_spec[((size_t)blockIdx.x * 2 + tok) * NFREQ + f] = sqrtf(re * re + im * im) * 0.005f;
    }
}

// ---------------------------------------------------------------------------
__global__ __launch_bounds__(256) void k_mkpe(const float* __restrict__ gns,
                                              const float* __restrict__ gnb,
                                              const float* __restrict__ spec_b) {
    int i = blockIdx.x * 256 + threadIdx.x;
    if (i >= PETOT) return;
    int tkn = i / DMD, d = i % DMD;
    int b = tkn / RR, r = tkn % RR;
    int ic = d >> 3;
    int bg = b * 5 + ic / 5;
    float raw = g_bufA[(((size_t)b * C25 + ic) * RR + r) * W8 + (d & 7)];
    float v = (raw - g_mean[bg]) * g_rstd[bg] * gns[ic] + gnb[ic];
    g_pe[i] = gelu_exact(v) + spec_b[d];
}

// ---------------------------------------------------------------------------
// generic fp32 SGEMM (spectral projection only): C += A @ B
// ---------------------------------------------------------------------------
__global__ __launch_bounds__(256) void k_sgemm(const float* __restrict__ A,
                                               const float* __restrict__ Bm,
                                               float* __restrict__ C,
                                               int M, int N, int K,
                                               int lda, int bk, int bn, int ldc,
                                               int accFlag) {
    __shared__ __align__(16) float As[8][68];
    __shared__ __align__(16) float Bs[8][68];
    int m0 = blockIdx.y * 64, n0 = blockIdx.x * 64;
    int t = threadIdx.x;
    int tx = t % 16, ty = t / 16;
    float acc[4][4];
    #pragma unroll
    for (int i = 0; i < 4; i++)
        #pragma unroll
        for (int j = 0; j < 4; j++) acc[i][j] = 0.f;

    int nk = (K + 7) / 8;
    for (int kb = 0; kb < nk; kb++) {
        int k0 = kb * 8;
        {
            int kk = t & 7, mm = t >> 3;
            int k = k0 + kk;
            #pragma unroll
            for (int hh = 0; hh < 2; hh++) {
                int m = m0 + mm + hh * 32;
                As[kk][mm + hh * 32] = (k < K && m < M) ? A[(size_t)m * lda + k] : 0.f;
            }
        }
        {
            int kk = t & 7, nn = t >> 3;
            int k = k0 + kk;
            #pragma unroll
            for (int hh = 0; hh < 2; hh++) {
                int n = n0 + nn + hh * 32;
                Bs[kk][nn + hh * 32] = (k < K && n < N) ? Bm[(size_t)k * bk + (size_t)n * bn] : 0.f;
            }
        }
        __syncthreads();
        #pragma unroll
        for (int kk = 0; kk < 8; kk++) {
            float4 av = *reinterpret_cast<const float4*>(&As[kk][ty * 4]);
            float4 bv = *reinterpret_cast<const float4*>(&Bs[kk][tx * 4]);
            float a[4] = {av.x, av.y, av.z, av.w};
            float bb[4] = {bv.x, bv.y, bv.z, bv.w};
            #pragma unroll
            for (int i = 0; i < 4; i++)
                #pragma unroll
                for (int j = 0; j < 4; j++) acc[i][j] += a[i] * bb[j];
        }
        __syncthreads();
    }
    #pragma unroll
    for (int i = 0; i < 4; i++) {
        int m = m0 + ty * 4 + i;
        if (m >= M) continue;
        #pragma unroll
        for (int j = 0; j < 4; j++) {
            int n = n0 + tx * 4 + j;
            if (n < N) {
                size_t o = (size_t)m * ldc + n;
                C[o] = accFlag ? (C[o] + acc[i][j]) : acc[i][j];
            }
        }
    }
}

// ---------------------------------------------------------------------------
__global__ __launch_bounds__(256) void k_c0(const float* __restrict__ cb,
                                            const float* __restrict__ inp_b) {
    int k = blockIdx.x;
    float s = 0.f, sb = 0.f;
    for (int l = threadIdx.x; l < LLM; l += 256) {
        float v = cb[(size_t)k * LLM + l];
        s += v * v;
        sb += inp_b[l] * v;
    }
    __shared__ float r1[256], r2[256];
    int t = threadIdx.x;
    r1[t] = s; r2[t] = sb;
    __syncthreads();
    for (int st = 128; st > 0; st >>= 1) {
        if (t < st) { r1[t] += r1[t + st]; r2[t] += r2[t + st]; }
        __syncthreads();
    }
    if (t == 0) g_c0[k] = 0.5f * r1[0] - r2[0];
}

// ---------------------------------------------------------------------------
// k_prep2: dual GEMM sharing A-tile (cb); MOV-free FMA2 inner loop.
//   G[m,n]    = sum_k cb[m,k] * inp_w[k,n]
//   cout[m,n] = sum_k cb[m,k] * outp_w[n,k]
// ---------------------------------------------------------------------------
__global__ __launch_bounds__(256) void k_prep2(const float* __restrict__ cb,
                                               const float* __restrict__ inp_w,
                                               const float* __restrict__ outp_w) {
    __shared__ __align__(16) unsigned long long As2[2][8][64];
    __shared__ __align__(16) float B1s[2][8][64];
    __shared__ __align__(16) float B2s[2][8][64];
    const int t = threadIdx.x;
    const int tx = t & 15, ty = t >> 4;
    const int lk = t & 7, lm = t >> 3;
    const int nn = t & 63, kq = t >> 6;
    const int m0 = blockIdx.y * 64, n0 = blockIdx.x * 64;

    unsigned long long a1[4][2], a2[4][2];
    #pragma unroll
    for (int i = 0; i < 4; i++)
        #pragma unroll
        for (int jp = 0; jp < 2; jp++) { a1[i][jp] = 0ULL; a2[i][jp] = 0ULL; }

    #pragma unroll
    for (int h = 0; h < 2; h++) {
        float a = cb[(size_t)(m0 + lm + h * 32) * LLM + lk];
        unsigned long long ad; PACKDUP(ad, a);
        As2[0][lk][lm + h * 32] = ad;
        int kk = kq + h * 4;
        B1s[0][kk][nn] = (n0 + nn < DMD) ? inp_w[(size_t)kk * DMD + n0 + nn] : 0.f;
        B2s[0][lk][lm + h * 32] = (n0 + lm + h * 32 < DMD)
            ? outp_w[(size_t)(n0 + lm + h * 32) * LLM + lk] : 0.f;
    }
    __syncthreads();
    for (int kb = 0; kb < LLM / 8; kb++) {
        int cur = kb & 1, nxt = cur ^ 1;
        if (kb < LLM / 8 - 1) {
            int k0 = (kb + 1) * 8;
            #pragma unroll
            for (int h = 0; h < 2; h++) {
                float a = cb[(size_t)(m0 + lm + h * 32) * LLM + k0 + lk];
                unsigned long long ad; PACKDUP(ad, a);
                As2[nxt][lk][lm + h * 32] = ad;
                int kk = kq + h * 4;
                B1s[nxt][kk][nn] = (n0 + nn < DMD) ? inp_w[(size_t)(k0 + kk) * DMD + n0 + nn] : 0.f;
                B2s[nxt][lk][lm + h * 32] = (n0 + lm + h * 32 < DMD)
                    ? outp_w[(size_t)(n0 + lm + h * 32) * LLM + k0 + lk] : 0.f;
            }
        }
        #pragma unroll
        for (int kk = 0; kk < 8; kk++) {
            ulonglong2 aA = *reinterpret_cast<const ulonglong2*>(&As2[cur][kk][ty * 4]);
            ulonglong2 aB = *reinterpret_cast<const ulonglong2*>(&As2[cur][kk][ty * 4 + 2]);
            ulonglong2 b1 = *reinterpret_cast<const ulonglong2*>(&B1s[cur][kk][tx * 4]);
            ulonglong2 b2 = *reinterpret_cast<const ulonglong2*>(&B2s[cur][kk][tx * 4]);
            unsigned long long ap[4] = {aA.x, aA.y, aB.x, aB.y};
            #pragma unroll
            for (int i = 0; i < 4; i++) {
                FMA2(a1[i][0], ap[i], b1.x);
                FMA2(a1[i][1], ap[i], b1.y);
                FMA2(a2[i][0], ap[i], b2.x);
                FMA2(a2[i][1], ap[i], b2.y);
            }
        }
        __syncthreads();
    }
    #pragma unroll
    for (int i = 0; i < 4; i++) {
        int m = m0 + ty * 4 + i;
        #pragma unroll
        for (int jp = 0; jp < 2; jp++) {
            unsigned lo, hi;
            int n = n0 + tx * 4 + jp * 2;
            UNPK2(lo, hi, a1[i][jp]);
            if (n < DMD)     g_G[(size_t)m * DMD + n]     = __uint_as_float(lo);
            if (n + 1 < DMD) g_G[(size_t)m * DMD + n + 1] = __uint_as_float(hi);
            UNPK2(lo, hi, a2[i][jp]);
            if (n < DMD)     g_cout[(size_t)m * DMD + n]     = __uint_as_float(lo);
            if (n + 1 < DMD) g_cout[(size_t)m * DMD + n + 1] = __uint_as_float(hi);
        }
    }
}

// ---------------------------------------------------------------------------
__global__ __launch_bounds__(256) void k_pos(const float* __restrict__ pw,
                                             const float* __restrict__ pb) {
    int b = blockIdx.x / DMD, d = blockIdx.x % DMD;
    __shared__ float mp[RR];
    __shared__ float w[133];
    int t = threadIdx.x;
    for (int i = t; i < RR; i += 256)
        mp[i] = g_pe[((size_t)b * RR + i) * DMD + d];
    if (t < 133) w[t] = pw[d * 133 + t];
    __syncthreads();
    float bias = pb[d];
    for (int o = t; o < RR; o += 256) {
        int ch = o / NPP, pn = o % NPP;
        float acc = mp[o] + bias;
        #pragma unroll
        for (int i = 0; i < 19; i++) {
            int ci = ch + i - 9;
            if (ci < 0 || ci >= CHN) continue;
            int base = ci * NPP;
            #pragma unroll
            for (int j = 0; j < 7; j++) {
                int pj = pn + j - 3;
                if (pj < 0 || pj >= NPP) continue;
                acc += mp[base + pj] * w[i * 7 + j];
            }
        }
        g_bufA[((size_t)b * RR + o) * DMD + d] = acc;
    }
}

// ---------------------------------------------------------------------------
// k_score2b: R3's score2 shape (64M x 128N, micro 4x8, 16 u64 acc) with a
// MOV-free inner loop: A dup'd to u64 in smem, B read as ulonglong2.
// Bit-identical FMA sequence to R3's k_score2.
// ---------------------------------------------------------------------------
__global__ __launch_bounds__(256) void k_score2b() {
    __shared__ __align__(16) unsigned long long As2[2][8][64];   // 8 KB
    __shared__ __align__(16) float Bs[2][8][128];                // 8 KB
    __shared__ float rv[64][17];
    __shared__ int   rix[64][17];
    const int t = threadIdx.x;
    const int tx = t & 15, ty = t >> 4;
    const int lk = t & 7, lm = t >> 3;
    const int m0 = blockIdx.x * 64;
    float bestv[4]; int besti[4];
    #pragma unroll
    for (int i = 0; i < 4; i++) { bestv[i] = INFINITY; besti[i] = 0; }

    for (int nb = 0; nb < 32; nb++) {
        const int n0 = nb * 128;
        __syncthreads();
        unsigned long long accp[4][4];
        #pragma unroll
        for (int i = 0; i < 4; i++)
            #pragma unroll
            for (int jp = 0; jp < 4; jp++) accp[i][jp] = 0ULL;
        // prologue tile 0
        #pragma unroll
        for (int h = 0; h < 2; h++) {
            float a = g_bufA[(size_t)(m0 + lm + h * 32) * DMD + lk];
            unsigned long long ad; PACKDUP(ad, a);
            As2[0][lk][lm + h * 32] = ad;
        }
        #pragma unroll
        for (int h = 0; h < 4; h++)
            Bs[0][lk][lm + h * 32] = g_G[(size_t)(n0 + lm + h * 32) * DMD + lk];
        __syncthreads();
        for (int kb = 0; kb < 25; kb++) {
            int cur = kb & 1, nxt = cur ^ 1;
            if (kb < 24) {
                int k = (kb + 1) * 8 + lk;
                #pragma unroll
                for (int h = 0; h < 2; h++) {
                    float a = g_bufA[(size_t)(m0 + lm + h * 32) * DMD + k];
                    unsigned long long ad; PACKDUP(ad, a);
                    As2[nxt][lk][lm + h * 32] = ad;
                }
                #pragma unroll
                for (int h = 0; h < 4; h++)
                    Bs[nxt][lk][lm + h * 32] = g_G[(size_t)(n0 + lm + h * 32) * DMD + k];
            }
            #pragma unroll
            for (int kk = 0; kk < 8; kk++) {
                ulonglong2 aA = *reinterpret_cast<const ulonglong2*>(&As2[cur][kk][ty * 4]);
                ulonglong2 aB = *reinterpret_cast<const ulonglong2*>(&As2[cur][kk][ty * 4 + 2]);
                ulonglong2 bq0 = *reinterpret_cast<const ulonglong2*>(&Bs[cur][kk][tx * 8]);
                ulonglong2 bq1 = *reinterpret_cast<const ulonglong2*>(&Bs[cur][kk][tx * 8 + 4]);
                unsigned long long ap[4] = {aA.x, aA.y, aB.x, aB.y};
                #pragma unroll
                for (int i = 0; i < 4; i++) {
                    FMA2(accp[i][0], ap[i], bq0.x);
                    FMA2(accp[i][1], ap[i], bq0.y);
                    FMA2(accp[i][2], ap[i], bq1.x);
                    FMA2(accp[i][3], ap[i], bq1.y);
                }
            }
            __syncthreads();
        }
        // running argmin epilogue (ascending n = first-min tie-break)
        float4 cA = *reinterpret_cast<const float4*>(&g_c0[n0 + tx * 8]);
        float4 cB = *reinterpret_cast<const float4*>(&g_c0[n0 + tx * 8 + 4]);
        float cv[8] = {cA.x, cA.y, cA.z, cA.w, cB.x, cB.y, cB.z, cB.w};
        #pragma unroll
        for (int jp = 0; jp < 4; jp++) {
            int nl = tx * 8 + jp * 2;
            #pragma unroll
            for (int i = 0; i < 4; i++) {
                unsigned lo, hi;
                UNPK2(lo, hi, accp[i][jp]);
                float s0 = cv[2 * jp]     - __uint_as_float(lo);
                float s1 = cv[2 * jp + 1] - __uint_as_float(hi);
                if (s0 < bestv[i]) { bestv[i] = s0; besti[i] = n0 + nl; }
                if (s1 < bestv[i]) { bestv[i] = s1; besti[i] = n0 + nl + 1; }
            }
        }
    }
    #pragma unroll
    for (int i = 0; i < 4; i++) { rv[ty * 4 + i][tx] = bestv[i]; rix[ty * 4 + i][tx] = besti[i]; }
    __syncthreads();
    if (t < 64) {
        float bv = rv[t][0]; int bi_ = rix[t][0];
        #pragma unroll
        for (int xx = 1; xx < 16; xx++) {
            float v = rv[t][xx]; int ii = rix[t][xx];
            if (v < bv || (v == bv && ii < bi_)) { bv = v; bi_ = ii; }
        }
        g_idx[m0 + t] = bi_;
    }
}

// ---------------------------------------------------------------------------
__global__ __launch_bounds__(256) void k_gather(const float* __restrict__ outp_b,
                                                float* __restrict__ out) {
    int i = blockIdx.x * 256 + threadIdx.x;
    if (i >= PETOT) return;
    int tkn = i / DMD, d = i % DMD;
    out[i] = g_cout[(size_t)g_idx[tkn] * DMD + d] + outp_b[d];
}

// ---------------------------------------------------------------------------
extern "C" void kernel_launch(void* const* d_in, const int* in_sizes, int n_in,
                              void* d_out, int out_size) {
    const float* x      = (const float*)d_in[0];
    const float* c1w    = (const float*)d_in[1];
    const float* c1b    = (const float*)d_in[2];
    const float* gn1s   = (const float*)d_in[3];
    const float* gn1b   = (const float*)d_in[4];
    const float* c2w    = (const float*)d_in[5];
    const float* c2b    = (const float*)d_in[6];
    const float* gn2s   = (const float*)d_in[7];
    const float* gn2b   = (const float*)d_in[8];
    const float* c3w    = (const float*)d_in[9];
    const float* c3b    = (const float*)d_in[10];
    const float* gn3s   = (const float*)d_in[11];
    const float* gn3b   = (const float*)d_in[12];
    const float* spec_w = (const float*)d_in[13];
    const float* spec_b = (const float*)d_in[14];
    const float* pos_w  = (const float*)d_in[15];
    const float* pos_b  = (const float*)d_in[16];
    const float* inp_w  = (const float*)d_in[17];
    const float* inp_b  = (const float*)d_in[18];
    const float* cb     = (const float*)d_in[19];
    const float* outp_w = (const float*)d_in[20];
    const float* outp_b = (const float*)d_in[21];
    float* out = (float*)d_out;

    float *pSpec, *pBufA, *pBufB, *pPe;
    cudaGetSymbolAddress((void**)&pSpec, g_spec);
    cudaGetSymbolAddress((void**)&pBufA, g_bufA);
    cudaGetSymbolAddress((void**)&pBufB, g_bufB);
    cudaGetSymbolAddress((void**)&pPe,   g_pe);

    const int EW = (HTOT + 255) / 256;

    // Launch order arranged so k_prep2 is launch #6 (ncu -s 5 -c 1 captures it).
    k_conv1<<<TT, 256>>>(x, c1w, c1b);                               // 1
    k_gnstats<<<BB * 5, 256>>>(pBufA);                               // 2
    k_conv3x<<<BB * 72, 256>>>(pBufA, c2w, c2b, gn1s, gn1b, pBufB);  // 3
    k_gnstats<<<BB * 5, 256>>>(pBufB);                               // 4
    k_conv3x<<<BB * 72, 256>>>(pBufB, c3w, c3b, gn2s, gn2b, pBufA);  // 5
    k_prep2<<<dim3(4, 64), 256>>>(cb, inp_w, outp_w);                // 6 <- profiled
    k_gnstats<<<BB * 5, 256>>>(pBufA);                               // 7
    k_c0<<<KCB, 256>>>(cb, inp_b);                                   // 8
    k_dft<<<TT / 2, 256>>>(x);                                       // 9
    k_mkpe<<<EW, 256>>>(gn3s, gn3b, spec_b);                         // 10
    k_sgemm<<<dim3((DMD + 63) / 64, TT / 64), 256>>>(pSpec, spec_w, pPe,
        TT, DMD, NFREQ, NFREQ, 1, NFREQ, DMD, 1);                    // 11
    k_pos<<<BB * DMD, 256>>>(pos_w, pos_b);                          // 12
    k_score2b<<<TT / 64, 256>>>();                                   // 13
    k_gather<<<EW, 256>>>(outp_b, out);                              // 14
}

// round 7
// speedup vs baseline: 1.7669x; 1.7669x over previous
#include <cuda_runtime.h>
#include <cuda_bf16.h>
#include <math.h>
#include <cstdint>

// ---------------------------------------------------------------------------
// CSBrainLLMVQ. Exact fp32 path for everything feeding the output.
//   score[t,k] = 0.5*||cb_k||^2 - inp_b.cb_k - pe2[t].G[k],  G = cb @ inp_w
//   out[t]     = code_out[idx[t]] + outp_b,   code_out = cb @ outp_w.T
// VQ argmin:
//   phase1: mma.sync bf16 2-split (A'=[Ph|Ph|Pl], B'=[Gh|Gl|Gh]) -> approx
//           scores, |err| <= ~5e-5
//   phase2: per-token candidates within MARGIN=4e-3 of approx min, exact
//           fp32 sequential rescore (bit-identical chain to the R3 scalar
//           kernel) -> idx identical to R3's.
// ---------------------------------------------------------------------------

#define BB   32
#define CHN  19
#define NPP  30
#define PSZ  200
#define RR   570
#define TT   18240
#define TTP  18304            // 143*128
#define DMD  200
#define LLM  4096
#define KCB  4096
#define C25  25
#define W8   8
#define HTOT (BB*C25*RR*W8)
#define PETOT (TT*DMD)
#define NFREQ 101
#define KPAD 640
#define MARGIN 4e-3f

__device__ float g_bufA[HTOT];
__device__ float g_bufB[HTOT];
__device__ float g_pe[PETOT];
__device__ float g_spec[TT*NFREQ];
__device__ float g_G[KCB*DMD];
__device__ float g_c0[KCB];
__device__ float g_cout[KCB*DMD];
__device__ int   g_idx[TT];
__device__ float g_mean[BB*5];
__device__ float g_rstd[BB*5];
__device__ __nv_bfloat16 g_A2[(size_t)TTP*KPAD];
__device__ __nv_bfloat16 g_B2[(size_t)KCB*KPAD];
__device__ float g_sapprox[(size_t)TTP*KCB];

__device__ __forceinline__ float gelu_exact(float v) {
    return 0.5f * v * (1.0f + erff(v * 0.70710678118654752f));
}

#define PACKDUP(dst, a) \
    asm("mov.b64 %0, {%1, %1};" : "=l"(dst) : "r"(__float_as_uint(a)))
#define PACK2(dst, a, b) \
    asm("mov.b64 %0, {%1, %2};" : "=l"(dst) : "r"(__float_as_uint(a)), "r"(__float_as_uint(b)))
#define FMA2(acc, a, b) \
    asm("fma.rn.f32x2 %0, %1, %2, %0;" : "+l"(acc) : "l"(a), "l"(b))
#define UNPK2(lo, hi, v) \
    asm("mov.b64 {%0, %1}, %2;" : "=r"(lo), "=r"(hi) : "l"(v))

// ---------------------------------------------------------------------------
__global__ __launch_bounds__(256) void k_conv1(const float* __restrict__ x,
                                               const float* __restrict__ w,
                                               const float* __restrict__ bias) {
    int br = blockIdx.x;
    int b = br / RR, r = br % RR;
    __shared__ float xs[PSZ];
    __shared__ float ws[C25 * 49];
    __shared__ float bs[C25];
    int t = threadIdx.x;
    if (t < PSZ) xs[t] = x[(size_t)br * PSZ + t];
    for (int i = t; i < C25 * 49; i += 256) ws[i] = w[i];
    if (t < C25) bs[t] = bias[t];
    __syncthreads();
    if (t < 200) {
        int oc = t >> 3, ow = t & 7;
        float acc = bs[oc];
        int base = ow * 25 - 24;
        #pragma unroll 7
        for (int k = 0; k < 49; k++) {
            int p = base + k;
            if (p >= 0 && p < PSZ) acc += xs[p] * ws[oc * 49 + k];
        }
        g_bufA[(((size_t)b * C25 + oc) * RR + r) * W8 + ow] = acc;
    }
}

// ---------------------------------------------------------------------------
__global__ __launch_bounds__(256) void k_gnstats(const float* __restrict__ h) {
    int bg = blockIdx.x;
    int b = bg / 5, g = bg % 5;
    float s1 = 0.f, s2 = 0.f;
    const int per = RR * W8;
    for (int i = threadIdx.x; i < 5 * per; i += 256) {
        int oc = g * 5 + i / per;
        int rw = i % per;
        float v = h[(size_t)(b * C25 + oc) * per + rw];
        s1 += v; s2 += v * v;
    }
    __shared__ float r1[256], r2[256];
    int t = threadIdx.x;
    r1[t] = s1; r2[t] = s2;
    __syncthreads();
    for (int s = 128; s > 0; s >>= 1) {
        if (t < s) { r1[t] += r1[t + s]; r2[t] += r2[t + s]; }
        __syncthreads();
    }
    if (t == 0) {
        float m = r1[0] / 22800.f;
        float var = r2[0] / 22800.f - m * m;
        g_mean[bg] = m;
        g_rstd[bg] = rsqrtf(var + 1e-5f);
    }
}

// ---------------------------------------------------------------------------
__global__ __launch_bounds__(256) void k_conv3x(const float* __restrict__ in,
                                                const float* __restrict__ w,
                                                const float* __restrict__ bias,
                                                const float* __restrict__ gns,
                                                const float* __restrict__ gnb,
                                                float* __restrict__ out) {
    int bi = blockIdx.x;
    int b = bi / 72, rt = bi % 72;
    int r0 = rt * 8;
    int nrows = min(8, RR - r0);
    __shared__ float sIn[C25][8][W8];
    __shared__ float sW[C25 * C25 * 3];
    __shared__ float sB[C25];
    __shared__ float sMean[C25], sRstd[C25], sSc[C25], sBi[C25];
    int t = threadIdx.x;
    for (int i = t; i < C25 * C25 * 3; i += 256) sW[i] = w[i];
    if (t < C25) {
        sB[t] = bias[t];
        int bg = b * 5 + t / 5;
        sMean[t] = g_mean[bg];
        sRstd[t] = g_rstd[bg];
        sSc[t]   = gns[t];
        sBi[t]   = gnb[t];
    }
    for (int i = t; i < C25 * nrows * W8; i += 256) {
        int ic = i / (nrows * W8);
        int lr = (i / W8) % nrows;
        int ww = i & 7;
        sIn[ic][lr][ww] = in[(((size_t)b * C25 + ic) * RR + r0 + lr) * W8 + ww];
    }
    __syncthreads();
    for (int i = t; i < C25 * nrows * W8; i += 256) {
        int ic = i / (nrows * W8);
        int lr = (i / W8) % nrows;
        int ww = i & 7;
        float v = (sIn[ic][lr][ww] - sMean[ic]) * sRstd[ic] * sSc[ic] + sBi[ic];
        sIn[ic][lr][ww] = gelu_exact(v);
    }
    __syncthreads();
    if (t < 200) {
        int oc = t >> 3, ww = t & 7;
        for (int lr = 0; lr < nrows; lr++) {
            float acc = sB[oc];
            #pragma unroll
            for (int ic = 0; ic < C25; ic++) {
                const float* wp = &sW[(oc * C25 + ic) * 3];
                if (ww > 0) acc += sIn[ic][lr][ww - 1] * wp[0];
                acc += sIn[ic][lr][ww] * wp[1];
                if (ww < 7) acc += sIn[ic][lr][ww + 1] * wp[2];
            }
            out[(((size_t)b * C25 + oc) * RR + r0 + lr) * W8 + ww] = acc;
        }
    }
}

// ---------------------------------------------------------------------------
__global__ __launch_bounds__(256) void k_dft(const float* __restrict__ x) {
    __shared__ float xs[2][PSZ], twc[PSZ], tws[PSZ];
    int t = threadIdx.x;
    const float* xp = x + (size_t)blockIdx.x * (2 * PSZ);
    for (int i = t; i < 2 * PSZ; i += 256) ((float*)xs)[i] = xp[i];
    if (t < PSZ) {
        float ang = 6.283185307179586f * (float)t / 200.f;
        twc[t] = cosf(ang);
        tws[t] = sinf(ang);
    }
    __syncthreads();
    if (t < 2 * NFREQ) {
        int tok = t / NFREQ, f = t % NFREQ;
        const float* xv = xs[tok];
        float re = 0.f, im = 0.f;
        int m = 0;
        #pragma unroll 8
        for (int n = 0; n < PSZ; n++) {
            re += xv[n] * twc[m];
            im += xv[n] * tws[m];
            m += f;
            if (m >= PSZ) m -= PSZ;
        }
        g_spec[((size_t)blockIdx.x * 2 + tok) * NFREQ + f] = sqrtf(re * re + im * im) * 0.005f;
    }
}

// ---------------------------------------------------------------------------
__global__ __launch_bounds__(256) void k_mkpe(const float* __restrict__ gns,
                                              const float* __restrict__ gnb,
                                              const float* __restrict__ spec_b) {
    int i = blockIdx.x * 256 + threadIdx.x;
    if (i >= PETOT) return;
    int tkn = i / DMD, d = i % DMD;
    int b = tkn / RR, r = tkn % RR;
    int ic = d >> 3;
    int bg = b * 5 + ic / 5;
    float raw = g_bufA[(((size_t)b * C25 + ic) * RR + r) * W8 + (d & 7)];
    float v = (raw - g_mean[bg]) * g_rstd[bg] * gns[ic] + gnb[ic];
    g_pe[i] = gelu_exact(v) + spec_b[d];
}

// ---------------------------------------------------------------------------
__global__ __launch_bounds__(256) void k_sgemm(const float* __restrict__ A,
                                               const float* __restrict__ Bm,
                                               float* __restrict__ C,
                                               int M, int N, int K,
                                               int lda, int bk, int bn, int ldc,
                                               int accFlag) {
    __shared__ __align__(16) float As[8][68];
    __shared__ __align__(16) float Bs[8][68];
    int m0 = blockIdx.y * 64, n0 = blockIdx.x * 64;
    int t = threadIdx.x;
    int tx = t % 16, ty = t / 16;
    float acc[4][4];
    #pragma unroll
    for (int i = 0; i < 4; i++)
        #pragma unroll
        for (int j = 0; j < 4; j++) acc[i][j] = 0.f;

    int nk = (K + 7) / 8;
    for (int kb = 0; kb < nk; kb++) {
        int k0 = kb * 8;
        {
            int kk = t & 7, mm = t >> 3;
            int k = k0 + kk;
            #pragma unroll
            for (int hh = 0; hh < 2; hh++) {
                int m = m0 + mm + hh * 32;
                As[kk][mm + hh * 32] = (k < K && m < M) ? A[(size_t)m * lda + k] : 0.f;
            }
        }
        {
            int kk = t & 7, nn = t >> 3;
            int k = k0 + kk;
            #pragma unroll
            for (int hh = 0; hh < 2; hh++) {
                int n = n0 + nn + hh * 32;
                Bs[kk][nn + hh * 32] = (k < K && n < N) ? Bm[(size_t)k * bk + (size_t)n * bn] : 0.f;
            }
        }
        __syncthreads();
        #pragma unroll
        for (int kk = 0; kk < 8; kk++) {
            float4 av = *reinterpret_cast<const float4*>(&As[kk][ty * 4]);
            float4 bv = *reinterpret_cast<const float4*>(&Bs[kk][tx * 4]);
            float a[4] = {av.x, av.y, av.z, av.w};
            float bb[4] = {bv.x, bv.y, bv.z, bv.w};
            #pragma unroll
            for (int i = 0; i < 4; i++)
                #pragma unroll
                for (int j = 0; j < 4; j++) acc[i][j] += a[i] * bb[j];
        }
        __syncthreads();
    }
    #pragma unroll
    for (int i = 0; i < 4; i++) {
        int m = m0 + ty * 4 + i;
        if (m >= M) continue;
        #pragma unroll
        for (int j = 0; j < 4; j++) {
            int n = n0 + tx * 4 + j;
            if (n < N) {
                size_t o = (size_t)m * ldc + n;
                C[o] = accFlag ? (C[o] + acc[i][j]) : acc[i][j];
            }
        }
    }
}

// ---------------------------------------------------------------------------
__global__ __launch_bounds__(256) void k_c0(const float* __restrict__ cb,
                                            const float* __restrict__ inp_b) {
    int k = blockIdx.x;
    float s = 0.f, sb = 0.f;
    for (int l = threadIdx.x; l < LLM; l += 256) {
        float v = cb[(size_t)k * LLM + l];
        s += v * v;
        sb += inp_b[l] * v;
    }
    __shared__ float r1[256], r2[256];
    int t = threadIdx.x;
    r1[t] = s; r2[t] = sb;
    __syncthreads();
    for (int st = 128; st > 0; st >>= 1) {
        if (t < st) { r1[t] += r1[t + st]; r2[t] += r2[t + st]; }
        __syncthreads();
    }
    if (t == 0) g_c0[k] = 0.5f * r1[0] - r2[0];
}

// ---------------------------------------------------------------------------
// k_prep (R3-identical): dual GEMM sharing A-tile (cb); FMA2 + reg packing.
// ---------------------------------------------------------------------------
__global__ __launch_bounds__(256) void k_prep(const float* __restrict__ cb,
                                              const float* __restrict__ inp_w,
                                              const float* __restrict__ outp_w) {
    __shared__ __align__(16) float As[2][8][68];
    __shared__ __align__(16) float B1s[2][8][68];
    __shared__ __align__(16) float B2s[2][8][68];
    const int t = threadIdx.x;
    const int tx = t & 15, ty = t >> 4;
    const int lk = t & 7, lm = t >> 3;
    const int nn = t & 63, kq = t >> 6;
    const int m0 = blockIdx.y * 64, n0 = blockIdx.x * 64;

    unsigned long long a1[4][2], a2[4][2];
    #pragma unroll
    for (int i = 0; i < 4; i++)
        #pragma unroll
        for (int jp = 0; jp < 2; jp++) { a1[i][jp] = 0ULL; a2[i][jp] = 0ULL; }

    #pragma unroll
    for (int h = 0; h < 2; h++) {
        As[0][lk][lm + h * 32] = cb[(size_t)(m0 + lm + h * 32) * LLM + lk];
        int kk = kq + h * 4;
        B1s[0][kk][nn] = (n0 + nn < DMD) ? inp_w[(size_t)kk * DMD + n0 + nn] : 0.f;
        B2s[0][lk][lm + h * 32] = (n0 + lm + h * 32 < DMD)
            ? outp_w[(size_t)(n0 + lm + h * 32) * LLM + lk] : 0.f;
    }
    __syncthreads();
    for (int kb = 0; kb < LLM / 8; kb++) {
        int cur = kb & 1, nxt = cur ^ 1;
        if (kb < LLM / 8 - 1) {
            int k0 = (kb + 1) * 8;
            #pragma unroll
            for (int h = 0; h < 2; h++) {
                As[nxt][lk][lm + h * 32] = cb[(size_t)(m0 + lm + h * 32) * LLM + k0 + lk];
                int kk = kq + h * 4;
                B1s[nxt][kk][nn] = (n0 + nn < DMD) ? inp_w[(size_t)(k0 + kk) * DMD + n0 + nn] : 0.f;
                B2s[nxt][lk][lm + h * 32] = (n0 + lm + h * 32 < DMD)
                    ? outp_w[(size_t)(n0 + lm + h * 32) * LLM + k0 + lk] : 0.f;
            }
        }
        #pragma unroll
        for (int kk = 0; kk < 8; kk++) {
            float4 av = *reinterpret_cast<const float4*>(&As[cur][kk][ty * 4]);
            float4 b1 = *reinterpret_cast<const float4*>(&B1s[cur][kk][tx * 4]);
            float4 b2 = *reinterpret_cast<const float4*>(&B2s[cur][kk][tx * 4]);
            unsigned long long b1p[2], b2p[2];
            PACK2(b1p[0], b1.x, b1.y); PACK2(b1p[1], b1.z, b1.w);
            PACK2(b2p[0], b2.x, b2.y); PACK2(b2p[1], b2.z, b2.w);
            float aa[4] = {av.x, av.y, av.z, av.w};
            #pragma unroll
            for (int i = 0; i < 4; i++) {
                unsigned long long ap;
                PACKDUP(ap, aa[i]);
                FMA2(a1[i][0], ap, b1p[0]);
                FMA2(a1[i][1], ap, b1p[1]);
                FMA2(a2[i][0], ap, b2p[0]);
                FMA2(a2[i][1], ap, b2p[1]);
            }
        }
        __syncthreads();
    }
    #pragma unroll
    for (int i = 0; i < 4; i++) {
        int m = m0 + ty * 4 + i;
        #pragma unroll
        for (int jp = 0; jp < 2; jp++) {
            unsigned lo, hi;
            int n = n0 + tx * 4 + jp * 2;
            UNPK2(lo, hi, a1[i][jp]);
            if (n < DMD)     g_G[(size_t)m * DMD + n]     = __uint_as_float(lo);
            if (n + 1 < DMD) g_G[(size_t)m * DMD + n + 1] = __uint_as_float(hi);
            UNPK2(lo, hi, a2[i][jp]);
            if (n < DMD)     g_cout[(size_t)m * DMD + n]     = __uint_as_float(lo);
            if (n + 1 < DMD) g_cout[(size_t)m * DMD + n + 1] = __uint_as_float(hi);
        }
    }
}

// ---------------------------------------------------------------------------
__global__ __launch_bounds__(256) void k_pos(const float* __restrict__ pw,
                                             const float* __restrict__ pb) {
    int b = blockIdx.x / DMD, d = blockIdx.x % DMD;
    __shared__ float mp[RR];
    __shared__ float w[133];
    int t = threadIdx.x;
    for (int i = t; i < RR; i += 256)
        mp[i] = g_pe[((size_t)b * RR + i) * DMD + d];
    if (t < 133) w[t] = pw[d * 133 + t];
    __syncthreads();
    float bias = pb[d];
    for (int o = t; o < RR; o += 256) {
        int ch = o / NPP, pn = o % NPP;
        float acc = mp[o] + bias;
        #pragma unroll
        for (int i = 0; i < 19; i++) {
            int ci = ch + i - 9;
            if (ci < 0 || ci >= CHN) continue;
            int base = ci * NPP;
            #pragma unroll
            for (int j = 0; j < 7; j++) {
                int pj = pn + j - 3;
                if (pj < 0 || pj >= NPP) continue;
                acc += mp[base + pj] * w[i * 7 + j];
            }
        }
        g_bufA[((size_t)b * RR + o) * DMD + d] = acc;
    }
}

// ---------------------------------------------------------------------------
// bf16 2-split conversion: A' = [P_hi | P_hi | P_lo], B' = [G_hi | G_lo | G_hi]
// ---------------------------------------------------------------------------
__global__ __launch_bounds__(256) void k_cvtA() {
    size_t i = (size_t)blockIdx.x * 256 + threadIdx.x;
    if (i >= (size_t)TTP * KPAD) return;
    int t = (int)(i / KPAD), c = (int)(i % KPAD);
    __nv_bfloat16 v = __float2bfloat16(0.f);
    if (t < TT && c < 600) {
        int d = (c < 200) ? c : (c < 400 ? c - 200 : c - 400);
        float x = g_bufA[(size_t)t * DMD + d];
        __nv_bfloat16 h = __float2bfloat16(x);
        if (c < 400) v = h;
        else         v = __float2bfloat16(x - __bfloat162float(h));
    }
    g_A2[i] = v;
}

__global__ __launch_bounds__(256) void k_cvtB() {
    size_t i = (size_t)blockIdx.x * 256 + threadIdx.x;
    if (i >= (size_t)KCB * KPAD) return;
    int k = (int)(i / KPAD), c = (int)(i % KPAD);
    __nv_bfloat16 v = __float2bfloat16(0.f);
    if (c < 600) {
        int d = (c < 200) ? c : (c < 400 ? c - 200 : c - 400);
        float x = g_G[(size_t)k * DMD + d];
        __nv_bfloat16 h = __float2bfloat16(x);
        if (c < 200 || c >= 400) v = h;
        else v = __float2bfloat16(x - __bfloat162float(h));
    }
    g_B2[i] = v;
}

// ---------------------------------------------------------------------------
// phase1: approx scores via mma.sync m16n8k16 bf16->fp32 (HMMA fallback path;
// tcgen05 PTX is rejected by this harness's compute_103 PTX target).
// Block: 128M x 128N, 8 warps as 2x4 of 64Mx32N. K' = 640 in 10 chunks of 64.
// s_approx[t][n] = c0[n] - sum A'[t] B'[n].
// ---------------------------------------------------------------------------
#define SK 72   // smem k-stride (bf16) w/ pad

__device__ __forceinline__ void mma_bf16(float* c, uint32_t a0, uint32_t a1,
                                         uint32_t a2, uint32_t a3,
                                         uint32_t b0, uint32_t b1) {
    asm volatile(
        "mma.sync.aligned.m16n8k16.row.col.f32.bf16.bf16.f32 "
        "{%0,%1,%2,%3}, {%4,%5,%6,%7}, {%8,%9}, {%0,%1,%2,%3};"
        : "+f"(c[0]), "+f"(c[1]), "+f"(c[2]), "+f"(c[3])
        : "r"(a0), "r"(a1), "r"(a2), "r"(a3), "r"(b0), "r"(b1));
}

__global__ __launch_bounds__(256) void k_phase1() {
    __shared__ __nv_bfloat16 As[128][SK];
    __shared__ __nv_bfloat16 Bs[128][SK];
    const int t = threadIdx.x, wid = t >> 5, lane = t & 31;
    const int m0 = blockIdx.x * 128, n0 = blockIdx.y * 128;
    const int wm = wid >> 2, wn = wid & 3;      // 2 x 4 warp grid
    const int r = lane >> 2, cc = (lane & 3) * 2;

    float acc[4][4][4];
    #pragma unroll
    for (int mt = 0; mt < 4; mt++)
        #pragma unroll
        for (int nt = 0; nt < 4; nt++)
            #pragma unroll
            for (int q = 0; q < 4; q++) acc[mt][nt][q] = 0.f;

    for (int ch = 0; ch < 10; ch++) {
        // load A & B tiles (128 rows x 64 bf16 each), 4 float4/thread each
        #pragma unroll
        for (int s = 0; s < 4; s++) {
            int idx = t + s * 256;           // 0..1023
            int row = idx >> 3, q = idx & 7;
            *reinterpret_cast<float4*>(&As[row][q * 8]) =
                *reinterpret_cast<const float4*>(g_A2 + (size_t)(m0 + row) * KPAD + ch * 64 + q * 8);
            *reinterpret_cast<float4*>(&Bs[row][q * 8]) =
                *reinterpret_cast<const float4*>(g_B2 + (size_t)(n0 + row) * KPAD + ch * 64 + q * 8);
        }
        __syncthreads();
        #pragma unroll
        for (int ks = 0; ks < 4; ks++) {
            const int k0 = ks * 16;
            uint32_t a[4][4], b[4][2];
            #pragma unroll
            for (int mt = 0; mt < 4; mt++) {
                int rowA = wm * 64 + mt * 16 + r;
                a[mt][0] = *reinterpret_cast<const uint32_t*>(&As[rowA][k0 + cc]);
                a[mt][1] = *reinterpret_cast<const uint32_t*>(&As[rowA + 8][k0 + cc]);
                a[mt][2] = *reinterpret_cast<const uint32_t*>(&As[rowA][k0 + cc + 8]);
                a[mt][3] = *reinterpret_cast<const uint32_t*>(&As[rowA + 8][k0 + cc + 8]);
            }
            #pragma unroll
            for (int nt = 0; nt < 4; nt++) {
                int rowB = wn * 32 + nt * 8 + r;
                b[nt][0] = *reinterpret_cast<const uint32_t*>(&Bs[rowB][k0 + cc]);
                b[nt][1] = *reinterpret_cast<const uint32_t*>(&Bs[rowB][k0 + cc + 8]);
            }
            #pragma unroll
            for (int mt = 0; mt < 4; mt++)
                #pragma unroll
                for (int nt = 0; nt < 4; nt++)
                    mma_bf16(acc[mt][nt], a[mt][0], a[mt][1], a[mt][2], a[mt][3],
                             b[nt][0], b[nt][1]);
        }
        __syncthreads();
    }

    // epilogue: s = c0[n] - acc
    #pragma unroll
    for (int nt = 0; nt < 4; nt++) {
        int col = n0 + wn * 32 + nt * 8 + cc;
        float c0a = g_c0[col], c0b = g_c0[col + 1];
        #pragma unroll
        for (int mt = 0; mt < 4; mt++) {
            int row0 = m0 + wm * 64 + mt * 16 + r;
            if (row0 < TT) {
                float2 v = make_float2(c0a - acc[mt][nt][0], c0b - acc[mt][nt][1]);
                *reinterpret_cast<float2*>(&g_sapprox[(size_t)row0 * KCB + col]) = v;
            }
            if (row0 + 8 < TT) {
                float2 v = make_float2(c0a - acc[mt][nt][2], c0b - acc[mt][nt][3]);
                *reinterpret_cast<float2*>(&g_sapprox[(size_t)(row0 + 8) * KCB + col]) = v;
            }
        }
    }
}

// ---------------------------------------------------------------------------
// phase2: per-token (one warp each): approx min, candidates within MARGIN,
// EXACT fp32 sequential rescore (identical chain to R3) -> first-min idx.
// Coalesced sapprox scans (lane-interleaved).
// ---------------------------------------------------------------------------
__global__ __launch_bounds__(256) void k_select() {
    __shared__ int lists[8][64];
    int wid = threadIdx.x >> 5, lid = threadIdx.x & 31;
    int tt = blockIdx.x * 8 + wid;
    if (tt >= TT) return;
    const float* __restrict__ srow = g_sapprox + (size_t)tt * KCB;

    float vmin = INFINITY;
    for (int j = 0; j < 128; j++) vmin = fminf(vmin, srow[j * 32 + lid]);
    for (int o = 16; o; o >>= 1) vmin = fminf(vmin, __shfl_xor_sync(0xFFFFFFFFu, vmin, o));
    float thr = vmin + MARGIN;

    int cnt = 0;
    for (int j = 0; j < 128; j++) {
        int k = j * 32 + lid;
        bool c = (srow[k] <= thr);
        unsigned m = __ballot_sync(0xFFFFFFFFu, c);
        if (c) {
            int pos = cnt + __popc(m & ((1u << lid) - 1u));
            if (pos < 64) lists[wid][pos] = k;
        }
        cnt += __popc(m);
    }
    __syncwarp();

    const float* __restrict__ pe = g_bufA + (size_t)tt * DMD;
    float bv = INFINITY; int bk = 0;
    if (cnt <= 64) {
        for (int c = lid; c < cnt; c += 32) {
            int k = lists[wid][c];
            const float* gr = g_G + (size_t)k * DMD;
            float acc = 0.f;
            #pragma unroll 1
            for (int q = 0; q < DMD; q++) acc = fmaf(pe[q], gr[q], acc);
            float s = g_c0[k] - acc;
            if (s < bv || (s == bv && k < bk)) { bv = s; bk = k; }
        }
    } else {
        // full exact scan fallback (essentially never taken)
        for (int k = lid; k < KCB; k += 32) {
            const float* gr = g_G + (size_t)k * DMD;
            float acc = 0.f;
            #pragma unroll 1
            for (int q = 0; q < DMD; q++) acc = fmaf(pe[q], gr[q], acc);
            float s = g_c0[k] - acc;
            if (s < bv || (s == bv && k < bk)) { bv = s; bk = k; }
        }
    }
    for (int o = 16; o; o >>= 1) {
        float ov = __shfl_xor_sync(0xFFFFFFFFu, bv, o);
        int ok = __shfl_xor_sync(0xFFFFFFFFu, bk, o);
        if (ov < bv || (ov == bv && ok < bk)) { bv = ov; bk = ok; }
    }
    if (lid == 0) g_idx[tt] = bk;
}

// ---------------------------------------------------------------------------
__global__ __launch_bounds__(256) void k_gather(const float* __restrict__ outp_b,
                                                float* __restrict__ out) {
    int i = blockIdx.x * 256 + threadIdx.x;
    if (i >= PETOT) return;
    int tkn = i / DMD, d = i % DMD;
    out[i] = g_cout[(size_t)g_idx[tkn] * DMD + d] + outp_b[d];
}

// ---------------------------------------------------------------------------
extern "C" void kernel_launch(void* const* d_in, const int* in_sizes, int n_in,
                              void* d_out, int out_size) {
    const float* x      = (const float*)d_in[0];
    const float* c1w    = (const float*)d_in[1];
    const float* c1b    = (const float*)d_in[2];
    const float* gn1s   = (const float*)d_in[3];
    const float* gn1b   = (const float*)d_in[4];
    const float* c2w    = (const float*)d_in[5];
    const float* c2b    = (const float*)d_in[6];
    const float* gn2s   = (const float*)d_in[7];
    const float* gn2b   = (const float*)d_in[8];
    const float* c3w    = (const float*)d_in[9];
    const float* c3b    = (const float*)d_in[10];
    const float* gn3s   = (const float*)d_in[11];
    const float* gn3b   = (const float*)d_in[12];
    const float* spec_w = (const float*)d_in[13];
    const float* spec_b = (const float*)d_in[14];
    const float* pos_w  = (const float*)d_in[15];
    const float* pos_b  = (const float*)d_in[16];
    const float* inp_w  = (const float*)d_in[17];
    const float* inp_b  = (const float*)d_in[18];
    const float* cb     = (const float*)d_in[19];
    const float* outp_w = (const float*)d_in[20];
    const float* outp_b = (const float*)d_in[21];
    float* out = (float*)d_out;

    float *pSpec, *pBufA, *pBufB, *pPe;
    cudaGetSymbolAddress((void**)&pSpec, g_spec);
    cudaGetSymbolAddress((void**)&pBufA, g_bufA);
    cudaGetSymbolAddress((void**)&pBufB, g_bufB);
    cudaGetSymbolAddress((void**)&pPe,   g_pe);

    const int EW = (HTOT + 255) / 256;

    // --- codebook branch (exact fp32; feeds exact path) ---
    k_prep<<<dim3(4, 64), 256>>>(cb, inp_w, outp_w);
    k_c0<<<KCB, 256>>>(cb, inp_b);
    k_cvtB<<<(KCB * KPAD + 255) / 256, 256>>>();

    // --- conv / GN / GELU chain ---
    k_conv1<<<TT, 256>>>(x, c1w, c1b);
    k_gnstats<<<BB * 5, 256>>>(pBufA);
    k_conv3x<<<BB * 72, 256>>>(pBufA, c2w, c2b, gn1s, gn1b, pBufB);
    k_gnstats<<<BB * 5, 256>>>(pBufB);
    k_conv3x<<<BB * 72, 256>>>(pBufB, c3w, c3b, gn2s, gn2b, pBufA);
    k_gnstats<<<BB * 5, 256>>>(pBufA);

    // --- spectral branch ---
    k_dft<<<TT / 2, 256>>>(x);
    k_mkpe<<<EW, 256>>>(gn3s, gn3b, spec_b);
    k_sgemm<<<dim3((DMD + 63) / 64, TT / 64), 256>>>(pSpec, spec_w, pPe,
        TT, DMD, NFREQ, NFREQ, 1, NFREQ, DMD, 1);

    // --- depthwise positional conv (pe2 -> g_bufA) ---
    k_pos<<<BB * DMD, 256>>>(pos_w, pos_b);

    // --- VQ argmin: approx MMA + exact candidate rescore ---
    k_cvtA<<<(int)(((size_t)TTP * KPAD + 255) / 256), 256>>>();
    k_phase1<<<dim3(TTP / 128, KCB / 128), 256>>>();
    k_select<<<(TT + 7) / 8, 256>>>();

    // --- output gather ---
    k_gather<<<EW, 256>>>(outp_b, out);
}

// round 8
// speedup vs baseline: 1.9783x; 1.1196x over previous
#include <cuda_runtime.h>
#include <cuda_bf16.h>
#include <math.h>
#include <cstdint>

// ---------------------------------------------------------------------------
// CSBrainLLMVQ. Exact fp32 path for everything feeding the output.
//   score[t,k] = 0.5*||cb_k||^2 - inp_b.cb_k - pe2[t].G[k],  G = cb @ inp_w
//   out[t]     = code_out[idx[t]] + outp_b,   code_out = cb @ outp_w.T
// VQ argmin:
//   phase1: mma.sync bf16 2-split -> approx scores (|err| <= ~5e-5)
//   phase2: candidates within MARGIN=4e-3 of approx min, exact fp32
//           sequential rescore (R3-bit-identical chain) -> exact idx.
// R8: fork-join dual-stream overlap of the conv chain (stream 0) with the
//     independent codebook branch (stream s2). No numeric change.
// ---------------------------------------------------------------------------

#define BB   32
#define CHN  19
#define NPP  30
#define PSZ  200
#define RR   570
#define TT   18240
#define TTP  18304            // 143*128
#define DMD  200
#define LLM  4096
#define KCB  4096
#define C25  25
#define W8   8
#define HTOT (BB*C25*RR*W8)
#define PETOT (TT*DMD)
#define NFREQ 101
#define KPAD 640
#define MARGIN 4e-3f

__device__ float g_bufA[HTOT];
__device__ float g_bufB[HTOT];
__device__ float g_pe[PETOT];
__device__ float g_spec[TT*NFREQ];
__device__ float g_G[KCB*DMD];
__device__ float g_c0[KCB];
__device__ float g_cout[KCB*DMD];
__device__ int   g_idx[TT];
__device__ float g_mean[BB*5];
__device__ float g_rstd[BB*5];
__device__ __nv_bfloat16 g_A2[(size_t)TTP*KPAD];
__device__ __nv_bfloat16 g_B2[(size_t)KCB*KPAD];
__device__ float g_sapprox[(size_t)TTP*KCB];

__device__ __forceinline__ float gelu_exact(float v) {
    return 0.5f * v * (1.0f + erff(v * 0.70710678118654752f));
}

#define PACKDUP(dst, a) \
    asm("mov.b64 %0, {%1, %1};" : "=l"(dst) : "r"(__float_as_uint(a)))
#define PACK2(dst, a, b) \
    asm("mov.b64 %0, {%1, %2};" : "=l"(dst) : "r"(__float_as_uint(a)), "r"(__float_as_uint(b)))
#define FMA2(acc, a, b) \
    asm("fma.rn.f32x2 %0, %1, %2, %0;" : "+l"(acc) : "l"(a), "l"(b))
#define UNPK2(lo, hi, v) \
    asm("mov.b64 {%0, %1}, %2;" : "=r"(lo), "=r"(hi) : "l"(v))

// ---------------------------------------------------------------------------
__global__ __launch_bounds__(256) void k_conv1(const float* __restrict__ x,
                                               const float* __restrict__ w,
                                               const float* __restrict__ bias) {
    int br = blockIdx.x;
    int b = br / RR, r = br % RR;
    __shared__ float xs[PSZ];
    __shared__ float ws[C25 * 49];
    __shared__ float bs[C25];
    int t = threadIdx.x;
    if (t < PSZ) xs[t] = x[(size_t)br * PSZ + t];
    for (int i = t; i < C25 * 49; i += 256) ws[i] = w[i];
    if (t < C25) bs[t] = bias[t];
    __syncthreads();
    if (t < 200) {
        int oc = t >> 3, ow = t & 7;
        float acc = bs[oc];
        int base = ow * 25 - 24;
        #pragma unroll 7
        for (int k = 0; k < 49; k++) {
            int p = base + k;
            if (p >= 0 && p < PSZ) acc += xs[p] * ws[oc * 49 + k];
        }
        g_bufA[(((size_t)b * C25 + oc) * RR + r) * W8 + ow] = acc;
    }
}

// ---------------------------------------------------------------------------
__global__ __launch_bounds__(256) void k_gnstats(const float* __restrict__ h) {
    int bg = blockIdx.x;
    int b = bg / 5, g = bg % 5;
    float s1 = 0.f, s2 = 0.f;
    const int per = RR * W8;
    for (int i = threadIdx.x; i < 5 * per; i += 256) {
        int oc = g * 5 + i / per;
        int rw = i % per;
        float v = h[(size_t)(b * C25 + oc) * per + rw];
        s1 += v; s2 += v * v;
    }
    __shared__ float r1[256], r2[256];
    int t = threadIdx.x;
    r1[t] = s1; r2[t] = s2;
    __syncthreads();
    for (int s = 128; s > 0; s >>= 1) {
        if (t < s) { r1[t] += r1[t + s]; r2[t] += r2[t + s]; }
        __syncthreads();
    }
    if (t == 0) {
        float m = r1[0] / 22800.f;
        float var = r2[0] / 22800.f - m * m;
        g_mean[bg] = m;
        g_rstd[bg] = rsqrtf(var + 1e-5f);
    }
}

// ---------------------------------------------------------------------------
__global__ __launch_bounds__(256) void k_conv3x(const float* __restrict__ in,
                                                const float* __restrict__ w,
                                                const float* __restrict__ bias,
                                                const float* __restrict__ gns,
                                                const float* __restrict__ gnb,
                                                float* __restrict__ out) {
    int bi = blockIdx.x;
    int b = bi / 72, rt = bi % 72;
    int r0 = rt * 8;
    int nrows = min(8, RR - r0);
    __shared__ float sIn[C25][8][W8];
    __shared__ float sW[C25 * C25 * 3];
    __shared__ float sB[C25];
    __shared__ float sMean[C25], sRstd[C25], sSc[C25], sBi[C25];
    int t = threadIdx.x;
    for (int i = t; i < C25 * C25 * 3; i += 256) sW[i] = w[i];
    if (t < C25) {
        sB[t] = bias[t];
        int bg = b * 5 + t / 5;
        sMean[t] = g_mean[bg];
        sRstd[t] = g_rstd[bg];
        sSc[t]   = gns[t];
        sBi[t]   = gnb[t];
    }
    for (int i = t; i < C25 * nrows * W8; i += 256) {
        int ic = i / (nrows * W8);
        int lr = (i / W8) % nrows;
        int ww = i & 7;
        sIn[ic][lr][ww] = in[(((size_t)b * C25 + ic) * RR + r0 + lr) * W8 + ww];
    }
    __syncthreads();
    for (int i = t; i < C25 * nrows * W8; i += 256) {
        int ic = i / (nrows * W8);
        int lr = (i / W8) % nrows;
        int ww = i & 7;
        float v = (sIn[ic][lr][ww] - sMean[ic]) * sRstd[ic] * sSc[ic] + sBi[ic];
        sIn[ic][lr][ww] = gelu_exact(v);
    }
    __syncthreads();
    if (t < 200) {
        int oc = t >> 3, ww = t & 7;
        for (int lr = 0; lr < nrows; lr++) {
            float acc = sB[oc];
            #pragma unroll
            for (int ic = 0; ic < C25; ic++) {
                const float* wp = &sW[(oc * C25 + ic) * 3];
                if (ww > 0) acc += sIn[ic][lr][ww - 1] * wp[0];
                acc += sIn[ic][lr][ww] * wp[1];
                if (ww < 7) acc += sIn[ic][lr][ww + 1] * wp[2];
            }
            out[(((size_t)b * C25 + oc) * RR + r0 + lr) * W8 + ww] = acc;
        }
    }
}

// ---------------------------------------------------------------------------
__global__ __launch_bounds__(256) void k_dft(const float* __restrict__ x) {
    __shared__ float xs[2][PSZ], twc[PSZ], tws[PSZ];
    int t = threadIdx.x;
    const float* xp = x + (size_t)blockIdx.x * (2 * PSZ);
    for (int i = t; i < 2 * PSZ; i += 256) ((float*)xs)[i] = xp[i];
    if (t < PSZ) {
        float ang = 6.283185307179586f * (float)t / 200.f;
        twc[t] = cosf(ang);
        tws[t] = sinf(ang);
    }
    __syncthreads();
    if (t < 2 * NFREQ) {
        int tok = t / NFREQ, f = t % NFREQ;
        const float* xv = xs[tok];
        float re = 0.f, im = 0.f;
        int m = 0;
        #pragma unroll 8
        for (int n = 0; n < PSZ; n++) {
            re += xv[n] * twc[m];
            im += xv[n] * tws[m];
            m += f;
            if (m >= PSZ) m -= PSZ;
        }
        g_spec[((size_t)blockIdx.x * 2 + tok) * NFREQ + f] = sqrtf(re * re + im * im) * 0.005f;
    }
}

// ---------------------------------------------------------------------------
__global__ __launch_bounds__(256) void k_mkpe(const float* __restrict__ gns,
                                              const float* __restrict__ gnb,
                                              const float* __restrict__ spec_b) {
    int i = blockIdx.x * 256 + threadIdx.x;
    if (i >= PETOT) return;
    int tkn = i / DMD, d = i % DMD;
    int b = tkn / RR, r = tkn % RR;
    int ic = d >> 3;
    int bg = b * 5 + ic / 5;
    float raw = g_bufA[(((size_t)b * C25 + ic) * RR + r) * W8 + (d & 7)];
    float v = (raw - g_mean[bg]) * g_rstd[bg] * gns[ic] + gnb[ic];
    g_pe[i] = gelu_exact(v) + spec_b[d];
}

// ---------------------------------------------------------------------------
__global__ __launch_bounds__(256) void k_sgemm(const float* __restrict__ A,
                                               const float* __restrict__ Bm,
                                               float* __restrict__ C,
                                               int M, int N, int K,
                                               int lda, int bk, int bn, int ldc,
                                               int accFlag) {
    __shared__ __align__(16) float As[8][68];
    __shared__ __align__(16) float Bs[8][68];
    int m0 = blockIdx.y * 64, n0 = blockIdx.x * 64;
    int t = threadIdx.x;
    int tx = t % 16, ty = t / 16;
    float acc[4][4];
    #pragma unroll
    for (int i = 0; i < 4; i++)
        #pragma unroll
        for (int j = 0; j < 4; j++) acc[i][j] = 0.f;

    int nk = (K + 7) / 8;
    for (int kb = 0; kb < nk; kb++) {
        int k0 = kb * 8;
        {
            int kk = t & 7, mm = t >> 3;
            int k = k0 + kk;
            #pragma unroll
            for (int hh = 0; hh < 2; hh++) {
                int m = m0 + mm + hh * 32;
                As[kk][mm + hh * 32] = (k < K && m < M) ? A[(size_t)m * lda + k] : 0.f;
            }
        }
        {
            int kk = t & 7, nn = t >> 3;
            int k = k0 + kk;
            #pragma unroll
            for (int hh = 0; hh < 2; hh++) {
                int n = n0 + nn + hh * 32;
                Bs[kk][nn + hh * 32] = (k < K && n < N) ? Bm[(size_t)k * bk + (size_t)n * bn] : 0.f;
            }
        }
        __syncthreads();
        #pragma unroll
        for (int kk = 0; kk < 8; kk++) {
            float4 av = *reinterpret_cast<const float4*>(&As[kk][ty * 4]);
            float4 bv = *reinterpret_cast<const float4*>(&Bs[kk][tx * 4]);
            float a[4] = {av.x, av.y, av.z, av.w};
            float bb[4] = {bv.x, bv.y, bv.z, bv.w};
            #pragma unroll
            for (int i = 0; i < 4; i++)
                #pragma unroll
                for (int j = 0; j < 4; j++) acc[i][j] += a[i] * bb[j];
        }
        __syncthreads();
    }
    #pragma unroll
    for (int i = 0; i < 4; i++) {
        int m = m0 + ty * 4 + i;
        if (m >= M) continue;
        #pragma unroll
        for (int j = 0; j < 4; j++) {
            int n = n0 + tx * 4 + j;
            if (n < N) {
                size_t o = (size_t)m * ldc + n;
                C[o] = accFlag ? (C[o] + acc[i][j]) : acc[i][j];
            }
        }
    }
}

// ---------------------------------------------------------------------------
__global__ __launch_bounds__(256) void k_c0(const float* __restrict__ cb,
                                            const float* __restrict__ inp_b) {
    int k = blockIdx.x;
    float s = 0.f, sb = 0.f;
    for (int l = threadIdx.x; l < LLM; l += 256) {
        float v = cb[(size_t)k * LLM + l];
        s += v * v;
        sb += inp_b[l] * v;
    }
    __shared__ float r1[256], r2[256];
    int t = threadIdx.x;
    r1[t] = s; r2[t] = sb;
    __syncthreads();
    for (int st = 128; st > 0; st >>= 1) {
        if (t < st) { r1[t] += r1[t + st]; r2[t] += r2[t + st]; }
        __syncthreads();
    }
    if (t == 0) g_c0[k] = 0.5f * r1[0] - r2[0];
}

// ---------------------------------------------------------------------------
// k_prep (R3-identical): dual GEMM sharing A-tile (cb); FMA2 + reg packing.
// ---------------------------------------------------------------------------
__global__ __launch_bounds__(256) void k_prep(const float* __restrict__ cb,
                                              const float* __restrict__ inp_w,
                                              const float* __restrict__ outp_w) {
    __shared__ __align__(16) float As[2][8][68];
    __shared__ __align__(16) float B1s[2][8][68];
    __shared__ __align__(16) float B2s[2][8][68];
    const int t = threadIdx.x;
    const int tx = t & 15, ty = t >> 4;
    const int lk = t & 7, lm = t >> 3;
    const int nn = t & 63, kq = t >> 6;
    const int m0 = blockIdx.y * 64, n0 = blockIdx.x * 64;

    unsigned long long a1[4][2], a2[4][2];
    #pragma unroll
    for (int i = 0; i < 4; i++)
        #pragma unroll
        for (int jp = 0; jp < 2; jp++) { a1[i][jp] = 0ULL; a2[i][jp] = 0ULL; }

    #pragma unroll
    for (int h = 0; h < 2; h++) {
        As[0][lk][lm + h * 32] = cb[(size_t)(m0 + lm + h * 32) * LLM + lk];
        int kk = kq + h * 4;
        B1s[0][kk][nn] = (n0 + nn < DMD) ? inp_w[(size_t)kk * DMD + n0 + nn] : 0.f;
        B2s[0][lk][lm + h * 32] = (n0 + lm + h * 32 < DMD)
            ? outp_w[(size_t)(n0 + lm + h * 32) * LLM + lk] : 0.f;
    }
    __syncthreads();
    for (int kb = 0; kb < LLM / 8; kb++) {
        int cur = kb & 1, nxt = cur ^ 1;
        if (kb < LLM / 8 - 1) {
            int k0 = (kb + 1) * 8;
            #pragma unroll
            for (int h = 0; h < 2; h++) {
                As[nxt][lk][lm + h * 32] = cb[(size_t)(m0 + lm + h * 32) * LLM + k0 + lk];
                int kk = kq + h * 4;
                B1s[nxt][kk][nn] = (n0 + nn < DMD) ? inp_w[(size_t)(k0 + kk) * DMD + n0 + nn] : 0.f;
                B2s[nxt][lk][lm + h * 32] = (n0 + lm + h * 32 < DMD)
                    ? outp_w[(size_t)(n0 + lm + h * 32) * LLM + k0 + lk] : 0.f;
            }
        }
        #pragma unroll
        for (int kk = 0; kk < 8; kk++) {
            float4 av = *reinterpret_cast<const float4*>(&As[cur][kk][ty * 4]);
            float4 b1 = *reinterpret_cast<const float4*>(&B1s[cur][kk][tx * 4]);
            float4 b2 = *reinterpret_cast<const float4*>(&B2s[cur][kk][tx * 4]);
            unsigned long long b1p[2], b2p[2];
            PACK2(b1p[0], b1.x, b1.y); PACK2(b1p[1], b1.z, b1.w);
            PACK2(b2p[0], b2.x, b2.y); PACK2(b2p[1], b2.z, b2.w);
            float aa[4] = {av.x, av.y, av.z, av.w};
            #pragma unroll
            for (int i = 0; i < 4; i++) {
                unsigned long long ap;
                PACKDUP(ap, aa[i]);
                FMA2(a1[i][0], ap, b1p[0]);
                FMA2(a1[i][1], ap, b1p[1]);
                FMA2(a2[i][0], ap, b2p[0]);
                FMA2(a2[i][1], ap, b2p[1]);
            }
        }
        __syncthreads();
    }
    #pragma unroll
    for (int i = 0; i < 4; i++) {
        int m = m0 + ty * 4 + i;
        #pragma unroll
        for (int jp = 0; jp < 2; jp++) {
            unsigned lo, hi;
            int n = n0 + tx * 4 + jp * 2;
            UNPK2(lo, hi, a1[i][jp]);
            if (n < DMD)     g_G[(size_t)m * DMD + n]     = __uint_as_float(lo);
            if (n + 1 < DMD) g_G[(size_t)m * DMD + n + 1] = __uint_as_float(hi);
            UNPK2(lo, hi, a2[i][jp]);
            if (n < DMD)     g_cout[(size_t)m * DMD + n]     = __uint_as_float(lo);
            if (n + 1 < DMD) g_cout[(size_t)m * DMD + n + 1] = __uint_as_float(hi);
        }
    }
}

// ---------------------------------------------------------------------------
__global__ __launch_bounds__(256) void k_pos(const float* __restrict__ pw,
                                             const float* __restrict__ pb) {
    int b = blockIdx.x / DMD, d = blockIdx.x % DMD;
    __shared__ float mp[RR];
    __shared__ float w[133];
    int t = threadIdx.x;
    for (int i = t; i < RR; i += 256)
        mp[i] = g_pe[((size_t)b * RR + i) * DMD + d];
    if (t < 133) w[t] = pw[d * 133 + t];
    __syncthreads();
    float bias = pb[d];
    for (int o = t; o < RR; o += 256) {
        int ch = o / NPP, pn = o % NPP;
        float acc = mp[o] + bias;
        #pragma unroll
        for (int i = 0; i < 19; i++) {
            int ci = ch + i - 9;
            if (ci < 0 || ci >= CHN) continue;
            int base = ci * NPP;
            #pragma unroll
            for (int j = 0; j < 7; j++) {
                int pj = pn + j - 3;
                if (pj < 0 || pj >= NPP) continue;
                acc += mp[base + pj] * w[i * 7 + j];
            }
        }
        g_bufA[((size_t)b * RR + o) * DMD + d] = acc;
    }
}

// ---------------------------------------------------------------------------
// bf16 2-split conversion: A' = [P_hi | P_hi | P_lo], B' = [G_hi | G_lo | G_hi]
// ---------------------------------------------------------------------------
__global__ __launch_bounds__(256) void k_cvtA() {
    size_t i = (size_t)blockIdx.x * 256 + threadIdx.x;
    if (i >= (size_t)TTP * KPAD) return;
    int t = (int)(i / KPAD), c = (int)(i % KPAD);
    __nv_bfloat16 v = __float2bfloat16(0.f);
    if (t < TT && c < 600) {
        int d = (c < 200) ? c : (c < 400 ? c - 200 : c - 400);
        float x = g_bufA[(size_t)t * DMD + d];
        __nv_bfloat16 h = __float2bfloat16(x);
        if (c < 400) v = h;
        else         v = __float2bfloat16(x - __bfloat162float(h));
    }
    g_A2[i] = v;
}

__global__ __launch_bounds__(256) void k_cvtB() {
    size_t i = (size_t)blockIdx.x * 256 + threadIdx.x;
    if (i >= (size_t)KCB * KPAD) return;
    int k = (int)(i / KPAD), c = (int)(i % KPAD);
    __nv_bfloat16 v = __float2bfloat16(0.f);
    if (c < 600) {
        int d = (c < 200) ? c : (c < 400 ? c - 200 : c - 400);
        float x = g_G[(size_t)k * DMD + d];
        __nv_bfloat16 h = __float2bfloat16(x);
        if (c < 200 || c >= 400) v = h;
        else v = __float2bfloat16(x - __bfloat162float(h));
    }
    g_B2[i] = v;
}

// ---------------------------------------------------------------------------
// phase1: approx scores via mma.sync m16n8k16 bf16->fp32.
// Block: 128M x 128N, 8 warps as 2x4 of 64Mx32N. K' = 640 in 10 chunks of 64.
// ---------------------------------------------------------------------------
#define SK 72

__device__ __forceinline__ void mma_bf16(float* c, uint32_t a0, uint32_t a1,
                                         uint32_t a2, uint32_t a3,
                                         uint32_t b0, uint32_t b1) {
    asm volatile(
        "mma.sync.aligned.m16n8k16.row.col.f32.bf16.bf16.f32 "
        "{%0,%1,%2,%3}, {%4,%5,%6,%7}, {%8,%9}, {%0,%1,%2,%3};"
        : "+f"(c[0]), "+f"(c[1]), "+f"(c[2]), "+f"(c[3])
        : "r"(a0), "r"(a1), "r"(a2), "r"(a3), "r"(b0), "r"(b1));
}

__global__ __launch_bounds__(256) void k_phase1() {
    __shared__ __nv_bfloat16 As[128][SK];
    __shared__ __nv_bfloat16 Bs[128][SK];
    const int t = threadIdx.x, wid = t >> 5, lane = t & 31;
    const int m0 = blockIdx.x * 128, n0 = blockIdx.y * 128;
    const int wm = wid >> 2, wn = wid & 3;
    const int r = lane >> 2, cc = (lane & 3) * 2;

    float acc[4][4][4];
    #pragma unroll
    for (int mt = 0; mt < 4; mt++)
        #pragma unroll
        for (int nt = 0; nt < 4; nt++)
            #pragma unroll
            for (int q = 0; q < 4; q++) acc[mt][nt][q] = 0.f;

    for (int ch = 0; ch < 10; ch++) {
        #pragma unroll
        for (int s = 0; s < 4; s++) {
            int idx = t + s * 256;
            int row = idx >> 3, q = idx & 7;
            *reinterpret_cast<float4*>(&As[row][q * 8]) =
                *reinterpret_cast<const float4*>(g_A2 + (size_t)(m0 + row) * KPAD + ch * 64 + q * 8);
            *reinterpret_cast<float4*>(&Bs[row][q * 8]) =
                *reinterpret_cast<const float4*>(g_B2 + (size_t)(n0 + row) * KPAD + ch * 64 + q * 8);
        }
        __syncthreads();
        #pragma unroll
        for (int ks = 0; ks < 4; ks++) {
            const int k0 = ks * 16;
            uint32_t a[4][4], b[4][2];
            #pragma unroll
            for (int mt = 0; mt < 4; mt++) {
                int rowA = wm * 64 + mt * 16 + r;
                a[mt][0] = *reinterpret_cast<const uint32_t*>(&As[rowA][k0 + cc]);
                a[mt][1] = *reinterpret_cast<const uint32_t*>(&As[rowA + 8][k0 + cc]);
                a[mt][2] = *reinterpret_cast<const uint32_t*>(&As[rowA][k0 + cc + 8]);
                a[mt][3] = *reinterpret_cast<const uint32_t*>(&As[rowA + 8][k0 + cc + 8]);
            }
            #pragma unroll
            for (int nt = 0; nt < 4; nt++) {
                int rowB = wn * 32 + nt * 8 + r;
                b[nt][0] = *reinterpret_cast<const uint32_t*>(&Bs[rowB][k0 + cc]);
                b[nt][1] = *reinterpret_cast<const uint32_t*>(&Bs[rowB][k0 + cc + 8]);
            }
            #pragma unroll
            for (int mt = 0; mt < 4; mt++)
                #pragma unroll
                for (int nt = 0; nt < 4; nt++)
                    mma_bf16(acc[mt][nt], a[mt][0], a[mt][1], a[mt][2], a[mt][3],
                             b[nt][0], b[nt][1]);
        }
        __syncthreads();
    }

    #pragma unroll
    for (int nt = 0; nt < 4; nt++) {
        int col = n0 + wn * 32 + nt * 8 + cc;
        float c0a = g_c0[col], c0b = g_c0[col + 1];
        #pragma unroll
        for (int mt = 0; mt < 4; mt++) {
            int row0 = m0 + wm * 64 + mt * 16 + r;
            if (row0 < TT) {
                float2 v = make_float2(c0a - acc[mt][nt][0], c0b - acc[mt][nt][1]);
                *reinterpret_cast<float2*>(&g_sapprox[(size_t)row0 * KCB + col]) = v;
            }
            if (row0 + 8 < TT) {
                float2 v = make_float2(c0a - acc[mt][nt][2], c0b - acc[mt][nt][3]);
                *reinterpret_cast<float2*>(&g_sapprox[(size_t)(row0 + 8) * KCB + col]) = v;
            }
        }
    }
}

// ---------------------------------------------------------------------------
// phase2: per-token (one warp): approx min, candidates within MARGIN,
// EXACT fp32 sequential rescore (identical chain to R3) -> first-min idx.
// ---------------------------------------------------------------------------
__global__ __launch_bounds__(256) void k_select() {
    __shared__ int lists[8][64];
    int wid = threadIdx.x >> 5, lid = threadIdx.x & 31;
    int tt = blockIdx.x * 8 + wid;
    if (tt >= TT) return;
    const float* __restrict__ srow = g_sapprox + (size_t)tt * KCB;

    float vmin = INFINITY;
    for (int j = 0; j < 128; j++) vmin = fminf(vmin, srow[j * 32 + lid]);
    for (int o = 16; o; o >>= 1) vmin = fminf(vmin, __shfl_xor_sync(0xFFFFFFFFu, vmin, o));
    float thr = vmin + MARGIN;

    int cnt = 0;
    for (int j = 0; j < 128; j++) {
        int k = j * 32 + lid;
        bool c = (srow[k] <= thr);
        unsigned m = __ballot_sync(0xFFFFFFFFu, c);
        if (c) {
            int pos = cnt + __popc(m & ((1u << lid) - 1u));
            if (pos < 64) lists[wid][pos] = k;
        }
        cnt += __popc(m);
    }
    __syncwarp();

    const float* __restrict__ pe = g_bufA + (size_t)tt * DMD;
    float bv = INFINITY; int bk = 0;
    if (cnt <= 64) {
        for (int c = lid; c < cnt; c += 32) {
            int k = lists[wid][c];
            const float* gr = g_G + (size_t)k * DMD;
            float acc = 0.f;
            #pragma unroll 1
            for (int q = 0; q < DMD; q++) acc = fmaf(pe[q], gr[q], acc);
            float s = g_c0[k] - acc;
            if (s < bv || (s == bv && k < bk)) { bv = s; bk = k; }
        }
    } else {
        for (int k = lid; k < KCB; k += 32) {
            const float* gr = g_G + (size_t)k * DMD;
            float acc = 0.f;
            #pragma unroll 1
            for (int q = 0; q < DMD; q++) acc = fmaf(pe[q], gr[q], acc);
            float s = g_c0[k] - acc;
            if (s < bv || (s == bv && k < bk)) { bv = s; bk = k; }
        }
    }
    for (int o = 16; o; o >>= 1) {
        float ov = __shfl_xor_sync(0xFFFFFFFFu, bv, o);
        int ok = __shfl_xor_sync(0xFFFFFFFFu, bk, o);
        if (ov < bv || (ov == bv && ok < bk)) { bv = ov; bk = ok; }
    }
    if (lid == 0) g_idx[tt] = bk;
}

// ---------------------------------------------------------------------------
__global__ __launch_bounds__(256) void k_gather(const float* __restrict__ outp_b,
                                                float* __restrict__ out) {
    int i = blockIdx.x * 256 + threadIdx.x;
    if (i >= PETOT) return;
    int tkn = i / DMD, d = i % DMD;
    out[i] = g_cout[(size_t)g_idx[tkn] * DMD + d] + outp_b[d];
}

// ---------------------------------------------------------------------------
extern "C" void kernel_launch(void* const* d_in, const int* in_sizes, int n_in,
                              void* d_out, int out_size) {
    const float* x      = (const float*)d_in[0];
    const float* c1w    = (const float*)d_in[1];
    const float* c1b    = (const float*)d_in[2];
    const float* gn1s   = (const float*)d_in[3];
    const float* gn1b   = (const float*)d_in[4];
    const float* c2w    = (const float*)d_in[5];
    const float* c2b    = (const float*)d_in[6];
    const float* gn2s   = (const float*)d_in[7];
    const float* gn2b   = (const float*)d_in[8];
    const float* c3w    = (const float*)d_in[9];
    const float* c3b    = (const float*)d_in[10];
    const float* gn3s   = (const float*)d_in[11];
    const float* gn3b   = (const float*)d_in[12];
    const float* spec_w = (const float*)d_in[13];
    const float* spec_b = (const float*)d_in[14];
    const float* pos_w  = (const float*)d_in[15];
    const float* pos_b  = (const float*)d_in[16];
    const float* inp_w  = (const float*)d_in[17];
    const float* inp_b  = (const float*)d_in[18];
    const float* cb     = (const float*)d_in[19];
    const float* outp_w = (const float*)d_in[20];
    const float* outp_b = (const float*)d_in[21];
    float* out = (float*)d_out;

    // One-time resources (created on the uncaptured correctness call; the
    // same launches/work are issued on every call -> deterministic).
    static cudaStream_t s2 = nullptr;
    static cudaEvent_t evFork = nullptr, evJoin = nullptr;
    if (s2 == nullptr) {
        cudaStreamCreateWithFlags(&s2, cudaStreamNonBlocking);
        cudaEventCreateWithFlags(&evFork, cudaEventDisableTiming);
        cudaEventCreateWithFlags(&evJoin, cudaEventDisableTiming);
    }

    float *pSpec, *pBufA, *pBufB, *pPe;
    cudaGetSymbolAddress((void**)&pSpec, g_spec);
    cudaGetSymbolAddress((void**)&pBufA, g_bufA);
    cudaGetSymbolAddress((void**)&pBufB, g_bufB);
    cudaGetSymbolAddress((void**)&pPe,   g_pe);

    const int EW = (HTOT + 255) / 256;

    // ---- fork: codebook branch on s2 (independent of conv chain) ----
    cudaEventRecord(evFork, 0);
    cudaStreamWaitEvent(s2, evFork, 0);
    k_prep<<<dim3(4, 64), 256, 0, s2>>>(cb, inp_w, outp_w);
    k_c0<<<KCB, 256, 0, s2>>>(cb, inp_b);
    k_cvtB<<<(KCB * KPAD + 255) / 256, 256, 0, s2>>>();

    // ---- main stream: conv / GN / GELU chain + spectral + pos + cvtA ----
    k_conv1<<<TT, 256>>>(x, c1w, c1b);
    k_gnstats<<<BB * 5, 256>>>(pBufA);
    k_conv3x<<<BB * 72, 256>>>(pBufA, c2w, c2b, gn1s, gn1b, pBufB);
    k_gnstats<<<BB * 5, 256>>>(pBufB);
    k_conv3x<<<BB * 72, 256>>>(pBufB, c3w, c3b, gn2s, gn2b, pBufA);
    k_gnstats<<<BB * 5, 256>>>(pBufA);
    k_dft<<<TT / 2, 256>>>(x);
    k_mkpe<<<EW, 256>>>(gn3s, gn3b, spec_b);
    k_sgemm<<<dim3((DMD + 63) / 64, TT / 64), 256>>>(pSpec, spec_w, pPe,
        TT, DMD, NFREQ, NFREQ, 1, NFREQ, DMD, 1);
    k_pos<<<BB * DMD, 256>>>(pos_w, pos_b);
    k_cvtA<<<(int)(((size_t)TTP * KPAD + 255) / 256), 256>>>();

    // ---- join: phase1 needs g_A2 (main) and g_B2/g_G/g_c0 (s2) ----
    cudaEventRecord(evJoin, s2);
    cudaStreamWaitEvent(0, evJoin, 0);

    k_phase1<<<dim3(TTP / 128, KCB / 128), 256>>>();
    k_select<<<(TT + 7) / 8, 256>>>();
    k_gather<<<EW, 256>>>(outp_b, out);
}

// round 9
// speedup vs baseline: 2.0625x; 1.0426x over previous
#include <cuda_runtime.h>
#include <cuda_bf16.h>
#include <cuda_fp16.h>
#include <math.h>
#include <cstdint>

// ---------------------------------------------------------------------------
// CSBrainLLMVQ. Exact fp32 path for everything feeding the output.
//   score[t,k] = 0.5*||cb_k||^2 - inp_b.cb_k - pe2[t].G[k],  G = cb @ inp_w
//   out[t]     = code_out[idx[t]] + outp_b,   code_out = cb @ outp_w.T
// VQ argmin:
//   phase1: mma.sync bf16 2-split -> approx scores (fp16-stored) + per-row
//           min via encoded atomicMin (g_rowmin)
//   phase2: single-pass candidate collection within MARGIN, exact fp32
//           sequential rescore (R3-bit-identical chain) -> exact idx.
// R9: fp16 sapprox + rowmin atomics, phase1 reg-prefetch, dft on 3rd stream,
//     branch-free padded conv1.
// ---------------------------------------------------------------------------

#define BB   32
#define CHN  19
#define NPP  30
#define PSZ  200
#define RR   570
#define TT   18240
#define TTP  18304            // 143*128
#define DMD  200
#define LLM  4096
#define KCB  4096
#define C25  25
#define W8   8
#define HTOT (BB*C25*RR*W8)
#define PETOT (TT*DMD)
#define NFREQ 101
#define KPAD 640
#define MARGIN 4e-3f

__device__ float g_bufA[HTOT];
__device__ float g_bufB[HTOT];
__device__ float g_pe[PETOT];
__device__ float g_spec[TT*NFREQ];
__device__ float g_G[KCB*DMD];
__device__ float g_c0[KCB];
__device__ float g_cout[KCB*DMD];
__device__ int   g_idx[TT];
__device__ float g_mean[BB*5];
__device__ float g_rstd[BB*5];
__device__ __nv_bfloat16 g_A2[(size_t)TTP*KPAD];
__device__ __nv_bfloat16 g_B2[(size_t)KCB*KPAD];
__device__ __half g_sap16[(size_t)TTP*KCB];
__device__ unsigned g_rowmin[TT];

__device__ __forceinline__ float gelu_exact(float v) {
    return 0.5f * v * (1.0f + erff(v * 0.70710678118654752f));
}

// order-preserving float <-> uint encode (for unsigned atomicMin)
__device__ __forceinline__ unsigned fenc(float f) {
    unsigned u = __float_as_uint(f);
    return (u & 0x80000000u) ? ~u : (u | 0x80000000u);
}
__device__ __forceinline__ float fdec(unsigned u) {
    unsigned b = (u & 0x80000000u) ? (u & 0x7FFFFFFFu) : ~u;
    return __uint_as_float(b);
}

#define PACKDUP(dst, a) \
    asm("mov.b64 %0, {%1, %1};" : "=l"(dst) : "r"(__float_as_uint(a)))
#define PACK2(dst, a, b) \
    asm("mov.b64 %0, {%1, %2};" : "=l"(dst) : "r"(__float_as_uint(a)), "r"(__float_as_uint(b)))
#define FMA2(acc, a, b) \
    asm("fma.rn.f32x2 %0, %1, %2, %0;" : "+l"(acc) : "l"(a), "l"(b))
#define UNPK2(lo, hi, v) \
    asm("mov.b64 {%0, %1}, %2;" : "=r"(lo), "=r"(hi) : "l"(v))

// ---------------------------------------------------------------------------
__global__ __launch_bounds__(256) void k_initmin() {
    int i = blockIdx.x * 256 + threadIdx.x;
    if (i < TT) g_rowmin[i] = 0xFFFFFFFFu;
}

// ---------------------------------------------------------------------------
// conv1 (branch-free via zero-padded smem; bit-identical: fma(0,w,acc)=acc)
// ---------------------------------------------------------------------------
__global__ __launch_bounds__(256) void k_conv1(const float* __restrict__ x,
                                               const float* __restrict__ w,
                                               const float* __restrict__ bias) {
    int br = blockIdx.x;
    int b = br / RR, r = br % RR;
    __shared__ float xs[248];          // 24 pad + 200 + 24 pad
    __shared__ float ws[C25 * 49];
    __shared__ float bs[C25];
    int t = threadIdx.x;
    if (t < 248) xs[t] = (t >= 24 && t < 224) ? x[(size_t)br * PSZ + t - 24] : 0.f;
    for (int i = t; i < C25 * 49; i += 256) ws[i] = w[i];
    if (t < C25) bs[t] = bias[t];
    __syncthreads();
    if (t < 200) {
        int oc = t >> 3, ow = t & 7;
        float acc = bs[oc];
        int base = ow * 25;            // padded index
        #pragma unroll 7
        for (int k = 0; k < 49; k++)
            acc += xs[base + k] * ws[oc * 49 + k];
        g_bufA[(((size_t)b * C25 + oc) * RR + r) * W8 + ow] = acc;
    }
}

// ---------------------------------------------------------------------------
__global__ __launch_bounds__(256) void k_gnstats(const float* __restrict__ h) {
    int bg = blockIdx.x;
    int b = bg / 5, g = bg % 5;
    float s1 = 0.f, s2 = 0.f;
    const int per = RR * W8;
    for (int i = threadIdx.x; i < 5 * per; i += 256) {
        int oc = g * 5 + i / per;
        int rw = i % per;
        float v = h[(size_t)(b * C25 + oc) * per + rw];
        s1 += v; s2 += v * v;
    }
    __shared__ float r1[256], r2[256];
    int t = threadIdx.x;
    r1[t] = s1; r2[t] = s2;
    __syncthreads();
    for (int s = 128; s > 0; s >>= 1) {
        if (t < s) { r1[t] += r1[t + s]; r2[t] += r2[t + s]; }
        __syncthreads();
    }
    if (t == 0) {
        float m = r1[0] / 22800.f;
        float var = r2[0] / 22800.f - m * m;
        g_mean[bg] = m;
        g_rstd[bg] = rsqrtf(var + 1e-5f);
    }
}

// ---------------------------------------------------------------------------
__global__ __launch_bounds__(256) void k_conv3x(const float* __restrict__ in,
                                                const float* __restrict__ w,
                                                const float* __restrict__ bias,
                                                const float* __restrict__ gns,
                                                const float* __restrict__ gnb,
                                                float* __restrict__ out) {
    int bi = blockIdx.x;
    int b = bi / 72, rt = bi % 72;
    int r0 = rt * 8;
    int nrows = min(8, RR - r0);
    __shared__ float sIn[C25][8][W8];
    __shared__ float sW[C25 * C25 * 3];
    __shared__ float sB[C25];
    __shared__ float sMean[C25], sRstd[C25], sSc[C25], sBi[C25];
    int t = threadIdx.x;
    for (int i = t; i < C25 * C25 * 3; i += 256) sW[i] = w[i];
    if (t < C25) {
        sB[t] = bias[t];
        int bg = b * 5 + t / 5;
        sMean[t] = g_mean[bg];
        sRstd[t] = g_rstd[bg];
        sSc[t]   = gns[t];
        sBi[t]   = gnb[t];
    }
    for (int i = t; i < C25 * nrows * W8; i += 256) {
        int ic = i / (nrows * W8);
        int lr = (i / W8) % nrows;
        int ww = i & 7;
        sIn[ic][lr][ww] = in[(((size_t)b * C25 + ic) * RR + r0 + lr) * W8 + ww];
    }
    __syncthreads();
    for (int i = t; i < C25 * nrows * W8; i += 256) {
        int ic = i / (nrows * W8);
        int lr = (i / W8) % nrows;
        int ww = i & 7;
        float v = (sIn[ic][lr][ww] - sMean[ic]) * sRstd[ic] * sSc[ic] + sBi[ic];
        sIn[ic][lr][ww] = gelu_exact(v);
    }
    __syncthreads();
    if (t < 200) {
        int oc = t >> 3, ww = t & 7;
        for (int lr = 0; lr < nrows; lr++) {
            float acc = sB[oc];
            #pragma unroll
            for (int ic = 0; ic < C25; ic++) {
                const float* wp = &sW[(oc * C25 + ic) * 3];
                if (ww > 0) acc += sIn[ic][lr][ww - 1] * wp[0];
                acc += sIn[ic][lr][ww] * wp[1];
                if (ww < 7) acc += sIn[ic][lr][ww + 1] * wp[2];
            }
            out[(((size_t)b * C25 + oc) * RR + r0 + lr) * W8 + ww] = acc;
        }
    }
}

// ---------------------------------------------------------------------------
__global__ __launch_bounds__(256) void k_dft(const float* __restrict__ x) {
    __shared__ float xs[2][PSZ], twc[PSZ], tws[PSZ];
    int t = threadIdx.x;
    const float* xp = x + (size_t)blockIdx.x * (2 * PSZ);
    for (int i = t; i < 2 * PSZ; i += 256) ((float*)xs)[i] = xp[i];
    if (t < PSZ) {
        float ang = 6.283185307179586f * (float)t / 200.f;
        twc[t] = cosf(ang);
        tws[t] = sinf(ang);
    }
    __syncthreads();
    if (t < 2 * NFREQ) {
        int tok = t / NFREQ, f = t % NFREQ;
        const float* xv = xs[tok];
        float re = 0.f, im = 0.f;
        int m = 0;
        #pragma unroll 8
        for (int n = 0; n < PSZ; n++) {
            re += xv[n] * twc[m];
            im += xv[n] * tws[m];
            m += f;
            if (m >= PSZ) m -= PSZ;
        }
        g_spec[((size_t)blockIdx.x * 2 + tok) * NFREQ + f] = sqrtf(re * re + im * im) * 0.005f;
    }
}

// ---------------------------------------------------------------------------
__global__ __launch_bounds__(256) void k_mkpe(const float* __restrict__ gns,
                                              const float* __restrict__ gnb,
                                              const float* __restrict__ spec_b) {
    int i = blockIdx.x * 256 + threadIdx.x;
    if (i >= PETOT) return;
    int tkn = i / DMD, d = i % DMD;
    int b = tkn / RR, r = tkn % RR;
    int ic = d >> 3;
    int bg = b * 5 + ic / 5;
    float raw = g_bufA[(((size_t)b * C25 + ic) * RR + r) * W8 + (d & 7)];
    float v = (raw - g_mean[bg]) * g_rstd[bg] * gns[ic] + gnb[ic];
    g_pe[i] = gelu_exact(v) + spec_b[d];
}

// ---------------------------------------------------------------------------
__global__ __launch_bounds__(256) void k_sgemm(const float* __restrict__ A,
                                               const float* __restrict__ Bm,
                                               float* __restrict__ C,
                                               int M, int N, int K,
                                               int lda, int bk, int bn, int ldc,
                                               int accFlag) {
    __shared__ __align__(16) float As[8][68];
    __shared__ __align__(16) float Bs[8][68];
    int m0 = blockIdx.y * 64, n0 = blockIdx.x * 64;
    int t = threadIdx.x;
    int tx = t % 16, ty = t / 16;
    float acc[4][4];
    #pragma unroll
    for (int i = 0; i < 4; i++)
        #pragma unroll
        for (int j = 0; j < 4; j++) acc[i][j] = 0.f;

    int nk = (K + 7) / 8;
    for (int kb = 0; kb < nk; kb++) {
        int k0 = kb * 8;
        {
            int kk = t & 7, mm = t >> 3;
            int k = k0 + kk;
            #pragma unroll
            for (int hh = 0; hh < 2; hh++) {
                int m = m0 + mm + hh * 32;
                As[kk][mm + hh * 32] = (k < K && m < M) ? A[(size_t)m * lda + k] : 0.f;
            }
        }
        {
            int kk = t & 7, nn = t >> 3;
            int k = k0 + kk;
            #pragma unroll
            for (int hh = 0; hh < 2; hh++) {
                int n = n0 + nn + hh * 32;
                Bs[kk][nn + hh * 32] = (k < K && n < N) ? Bm[(size_t)k * bk + (size_t)n * bn] : 0.f;
            }
        }
        __syncthreads();
        #pragma unroll
        for (int kk = 0; kk < 8; kk++) {
            float4 av = *reinterpret_cast<const float4*>(&As[kk][ty * 4]);
            float4 bv = *reinterpret_cast<const float4*>(&Bs[kk][tx * 4]);
            float a[4] = {av.x, av.y, av.z, av.w};
            float bb[4] = {bv.x, bv.y, bv.z, bv.w};
            #pragma unroll
            for (int i = 0; i < 4; i++)
                #pragma unroll
                for (int j = 0; j < 4; j++) acc[i][j] += a[i] * bb[j];
        }
        __syncthreads();
    }
    #pragma unroll
    for (int i = 0; i < 4; i++) {
        int m = m0 + ty * 4 + i;
        if (m >= M) continue;
        #pragma unroll
        for (int j = 0; j < 4; j++) {
            int n = n0 + tx * 4 + j;
            if (n < N) {
                size_t o = (size_t)m * ldc + n;
                C[o] = accFlag ? (C[o] + acc[i][j]) : acc[i][j];
            }
        }
    }
}

// ---------------------------------------------------------------------------
__global__ __launch_bounds__(256) void k_c0(const float* __restrict__ cb,
                                            const float* __restrict__ inp_b) {
    int k = blockIdx.x;
    float s = 0.f, sb = 0.f;
    for (int l = threadIdx.x; l < LLM; l += 256) {
        float v = cb[(size_t)k * LLM + l];
        s += v * v;
        sb += inp_b[l] * v;
    }
    __shared__ float r1[256], r2[256];
    int t = threadIdx.x;
    r1[t] = s; r2[t] = sb;
    __syncthreads();
    for (int st = 128; st > 0; st >>= 1) {
        if (t < st) { r1[t] += r1[t + st]; r2[t] += r2[t + st]; }
        __syncthreads();
    }
    if (t == 0) g_c0[k] = 0.5f * r1[0] - r2[0];
}

// ---------------------------------------------------------------------------
// k_prep (R3-identical): dual GEMM sharing A-tile (cb); FMA2 + reg packing.
// ---------------------------------------------------------------------------
__global__ __launch_bounds__(256) void k_prep(const float* __restrict__ cb,
                                              const float* __restrict__ inp_w,
                                              const float* __restrict__ outp_w) {
    __shared__ __align__(16) float As[2][8][68];
    __shared__ __align__(16) float B1s[2][8][68];
    __shared__ __align__(16) float B2s[2][8][68];
    const int t = threadIdx.x;
    const int tx = t & 15, ty = t >> 4;
    const int lk = t & 7, lm = t >> 3;
    const int nn = t & 63, kq = t >> 6;
    const int m0 = blockIdx.y * 64, n0 = blockIdx.x * 64;

    unsigned long long a1[4][2], a2[4][2];
    #pragma unroll
    for (int i = 0; i < 4; i++)
        #pragma unroll
        for (int jp = 0; jp < 2; jp++) { a1[i][jp] = 0ULL; a2[i][jp] = 0ULL; }

    #pragma unroll
    for (int h = 0; h < 2; h++) {
        As[0][lk][lm + h * 32] = cb[(size_t)(m0 + lm + h * 32) * LLM + lk];
        int kk = kq + h * 4;
        B1s[0][kk][nn] = (n0 + nn < DMD) ? inp_w[(size_t)kk * DMD + n0 + nn] : 0.f;
        B2s[0][lk][lm + h * 32] = (n0 + lm + h * 32 < DMD)
            ? outp_w[(size_t)(n0 + lm + h * 32) * LLM + lk] : 0.f;
    }
    __syncthreads();
    for (int kb = 0; kb < LLM / 8; kb++) {
        int cur = kb & 1, nxt = cur ^ 1;
        if (kb < LLM / 8 - 1) {
            int k0 = (kb + 1) * 8;
            #pragma unroll
            for (int h = 0; h < 2; h++) {
                As[nxt][lk][lm + h * 32] = cb[(size_t)(m0 + lm + h * 32) * LLM + k0 + lk];
                int kk = kq + h * 4;
                B1s[nxt][kk][nn] = (n0 + nn < DMD) ? inp_w[(size_t)(k0 + kk) * DMD + n0 + nn] : 0.f;
                B2s[nxt][lk][lm + h * 32] = (n0 + lm + h * 32 < DMD)
                    ? outp_w[(size_t)(n0 + lm + h * 32) * LLM + k0 + lk] : 0.f;
            }
        }
        #pragma unroll
        for (int kk = 0; kk < 8; kk++) {
            float4 av = *reinterpret_cast<const float4*>(&As[cur][kk][ty * 4]);
            float4 b1 = *reinterpret_cast<const float4*>(&B1s[cur][kk][tx * 4]);
            float4 b2 = *reinterpret_cast<const float4*>(&B2s[cur][kk][tx * 4]);
            unsigned long long b1p[2], b2p[2];
            PACK2(b1p[0], b1.x, b1.y); PACK2(b1p[1], b1.z, b1.w);
            PACK2(b2p[0], b2.x, b2.y); PACK2(b2p[1], b2.z, b2.w);
            float aa[4] = {av.x, av.y, av.z, av.w};
            #pragma unroll
            for (int i = 0; i < 4; i++) {
                unsigned long long ap;
                PACKDUP(ap, aa[i]);
                FMA2(a1[i][0], ap, b1p[0]);
                FMA2(a1[i][1], ap, b1p[1]);
                FMA2(a2[i][0], ap, b2p[0]);
                FMA2(a2[i][1], ap, b2p[1]);
            }
        }
        __syncthreads();
    }
    #pragma unroll
    for (int i = 0; i < 4; i++) {
        int m = m0 + ty * 4 + i;
        #pragma unroll
        for (int jp = 0; jp < 2; jp++) {
            unsigned lo, hi;
            int n = n0 + tx * 4 + jp * 2;
            UNPK2(lo, hi, a1[i][jp]);
            if (n < DMD)     g_G[(size_t)m * DMD + n]     = __uint_as_float(lo);
            if (n + 1 < DMD) g_G[(size_t)m * DMD + n + 1] = __uint_as_float(hi);
            UNPK2(lo, hi, a2[i][jp]);
            if (n < DMD)     g_cout[(size_t)m * DMD + n]     = __uint_as_float(lo);
            if (n + 1 < DMD) g_cout[(size_t)m * DMD + n + 1] = __uint_as_float(hi);
        }
    }
}

// ---------------------------------------------------------------------------
__global__ __launch_bounds__(256) void k_pos(const float* __restrict__ pw,
                                             const float* __restrict__ pb) {
    int b = blockIdx.x / DMD, d = blockIdx.x % DMD;
    __shared__ float mp[RR];
    __shared__ float w[133];
    int t = threadIdx.x;
    for (int i = t; i < RR; i += 256)
        mp[i] = g_pe[((size_t)b * RR + i) * DMD + d];
    if (t < 133) w[t] = pw[d * 133 + t];
    __syncthreads();
    float bias = pb[d];
    for (int o = t; o < RR; o += 256) {
        int ch = o / NPP, pn = o % NPP;
        float acc = mp[o] + bias;
        #pragma unroll
        for (int i = 0; i < 19; i++) {
            int ci = ch + i - 9;
            if (ci < 0 || ci >= CHN) continue;
            int base = ci * NPP;
            #pragma unroll
            for (int j = 0; j < 7; j++) {
                int pj = pn + j - 3;
                if (pj < 0 || pj >= NPP) continue;
                acc += mp[base + pj] * w[i * 7 + j];
            }
        }
        g_bufA[((size_t)b * RR + o) * DMD + d] = acc;
    }
}

// ---------------------------------------------------------------------------
// bf16 2-split conversion: A' = [P_hi | P_hi | P_lo], B' = [G_hi | G_lo | G_hi]
// ---------------------------------------------------------------------------
__global__ __launch_bounds__(256) void k_cvtA() {
    size_t i = (size_t)blockIdx.x * 256 + threadIdx.x;
    if (i >= (size_t)TTP * KPAD) return;
    int t = (int)(i / KPAD), c = (int)(i % KPAD);
    __nv_bfloat16 v = __float2bfloat16(0.f);
    if (t < TT && c < 600) {
        int d = (c < 200) ? c : (c < 400 ? c - 200 : c - 400);
        float x = g_bufA[(size_t)t * DMD + d];
        __nv_bfloat16 h = __float2bfloat16(x);
        if (c < 400) v = h;
        else         v = __float2bfloat16(x - __bfloat162float(h));
    }
    g_A2[i] = v;
}

__global__ __launch_bounds__(256) void k_cvtB() {
    size_t i = (size_t)blockIdx.x * 256 + threadIdx.x;
    if (i >= (size_t)KCB * KPAD) return;
    int k = (int)(i / KPAD), c = (int)(i % KPAD);
    __nv_bfloat16 v = __float2bfloat16(0.f);
    if (c < 600) {
        int d = (c < 200) ? c : (c < 400 ? c - 200 : c - 400);
        float x = g_G[(size_t)k * DMD + d];
        __nv_bfloat16 h = __float2bfloat16(x);
        if (c < 200 || c >= 400) v = h;
        else v = __float2bfloat16(x - __bfloat162float(h));
    }
    g_B2[i] = v;
}

// ---------------------------------------------------------------------------
// phase1: approx scores via mma.sync m16n8k16 bf16->fp32, register-prefetch
// pipeline, fp16 score store + per-row encoded atomicMin into g_rowmin.
// Block: 128M x 128N, 8 warps as 2x4 of 64Mx32N. K' = 640 in 10 chunks of 64.
// ---------------------------------------------------------------------------
#define SK 72

__device__ __forceinline__ void mma_bf16(float* c, uint32_t a0, uint32_t a1,
                                         uint32_t a2, uint32_t a3,
                                         uint32_t b0, uint32_t b1) {
    asm volatile(
        "mma.sync.aligned.m16n8k16.row.col.f32.bf16.bf16.f32 "
        "{%0,%1,%2,%3}, {%4,%5,%6,%7}, {%8,%9}, {%0,%1,%2,%3};"
        : "+f"(c[0]), "+f"(c[1]), "+f"(c[2]), "+f"(c[3])
        : "r"(a0), "r"(a1), "r"(a2), "r"(a3), "r"(b0), "r"(b1));
}

__global__ __launch_bounds__(256) void k_phase1() {
    __shared__ __nv_bfloat16 As[128][SK];
    __shared__ __nv_bfloat16 Bs[128][SK];
    __shared__ unsigned urmin[128];
    const int t = threadIdx.x, wid = t >> 5, lane = t & 31;
    const int m0 = blockIdx.x * 128, n0 = blockIdx.y * 128;
    const int wm = wid >> 2, wn = wid & 3;
    const int r = lane >> 2, cc = (lane & 3) * 2;
    const int lrow = t >> 3, lq = t & 7;     // load mapping: 32 rows x 8 q per 256

    if (t < 128) urmin[t] = 0xFFFFFFFFu;

    float acc[4][4][4];
    #pragma unroll
    for (int mt = 0; mt < 4; mt++)
        #pragma unroll
        for (int nt = 0; nt < 4; nt++)
            #pragma unroll
            for (int q = 0; q < 4; q++) acc[mt][nt][q] = 0.f;

    // prefetch chunk 0 into registers
    float4 pa[4], pb[4];
    #pragma unroll
    for (int s = 0; s < 4; s++) {
        int row = lrow + s * 32;
        pa[s] = *reinterpret_cast<const float4*>(g_A2 + (size_t)(m0 + row) * KPAD + lq * 8);
        pb[s] = *reinterpret_cast<const float4*>(g_B2 + (size_t)(n0 + row) * KPAD + lq * 8);
    }

    for (int ch = 0; ch < 10; ch++) {
        #pragma unroll
        for (int s = 0; s < 4; s++) {
            int row = lrow + s * 32;
            *reinterpret_cast<float4*>(&As[row][lq * 8]) = pa[s];
            *reinterpret_cast<float4*>(&Bs[row][lq * 8]) = pb[s];
        }
        __syncthreads();
        if (ch < 9) {
            #pragma unroll
            for (int s = 0; s < 4; s++) {
                int row = lrow + s * 32;
                pa[s] = *reinterpret_cast<const float4*>(
                    g_A2 + (size_t)(m0 + row) * KPAD + (ch + 1) * 64 + lq * 8);
                pb[s] = *reinterpret_cast<const float4*>(
                    g_B2 + (size_t)(n0 + row) * KPAD + (ch + 1) * 64 + lq * 8);
            }
        }
        #pragma unroll
        for (int ks = 0; ks < 4; ks++) {
            const int k0 = ks * 16;
            uint32_t a[4][4], b[4][2];
            #pragma unroll
            for (int mt = 0; mt < 4; mt++) {
                int rowA = wm * 64 + mt * 16 + r;
                a[mt][0] = *reinterpret_cast<const uint32_t*>(&As[rowA][k0 + cc]);
                a[mt][1] = *reinterpret_cast<const uint32_t*>(&As[rowA + 8][k0 + cc]);
                a[mt][2] = *reinterpret_cast<const uint32_t*>(&As[rowA][k0 + cc + 8]);
                a[mt][3] = *reinterpret_cast<const uint32_t*>(&As[rowA + 8][k0 + cc + 8]);
            }
            #pragma unroll
            for (int nt = 0; nt < 4; nt++) {
                int rowB = wn * 32 + nt * 8 + r;
                b[nt][0] = *reinterpret_cast<const uint32_t*>(&Bs[rowB][k0 + cc]);
                b[nt][1] = *reinterpret_cast<const uint32_t*>(&Bs[rowB][k0 + cc + 8]);
            }
            #pragma unroll
            for (int mt = 0; mt < 4; mt++)
                #pragma unroll
                for (int nt = 0; nt < 4; nt++)
                    mma_bf16(acc[mt][nt], a[mt][0], a[mt][1], a[mt][2], a[mt][3],
                             b[nt][0], b[nt][1]);
        }
        __syncthreads();
    }

    // epilogue: s = c0[n] - acc; fp16 store + row-min reduction
    #pragma unroll
    for (int mt = 0; mt < 4; mt++) {
        int lr0 = wm * 64 + mt * 16 + r;          // local rows lr0, lr0+8
        float mlo = INFINITY, mhi = INFINITY;
        #pragma unroll
        for (int nt = 0; nt < 4; nt++) {
            int col = n0 + wn * 32 + nt * 8 + cc;
            float c0a = g_c0[col], c0b = g_c0[col + 1];
            float s0 = c0a - acc[mt][nt][0], s1 = c0b - acc[mt][nt][1];
            float s2 = c0a - acc[mt][nt][2], s3 = c0b - acc[mt][nt][3];
            mlo = fminf(mlo, fminf(s0, s1));
            mhi = fminf(mhi, fminf(s2, s3));
            int row0 = m0 + lr0;
            if (row0 < TT)
                *reinterpret_cast<__half2*>(&g_sap16[(size_t)row0 * KCB + col]) =
                    __floats2half2_rn(s0, s1);
            if (row0 + 8 < TT)
                *reinterpret_cast<__half2*>(&g_sap16[(size_t)(row0 + 8) * KCB + col]) =
                    __floats2half2_rn(s2, s3);
        }
        atomicMin(&urmin[lr0], fenc(mlo));
        atomicMin(&urmin[lr0 + 8], fenc(mhi));
    }
    __syncthreads();
    if (t < 128 && m0 + t < TT)
        atomicMin(&g_rowmin[m0 + t], urmin[t]);
}

// ---------------------------------------------------------------------------
// phase2: per-token (one warp): thr from g_rowmin, single candidate pass
// over fp16 scores, EXACT fp32 sequential rescore -> first-min idx.
// ---------------------------------------------------------------------------
__global__ __launch_bounds__(256) void k_select() {
    __shared__ int lists[8][64];
    int wid = threadIdx.x >> 5, lid = threadIdx.x & 31;
    int tt = blockIdx.x * 8 + wid;
    if (tt >= TT) return;
    const __half2* __restrict__ srow =
        reinterpret_cast<const __half2*>(g_sap16 + (size_t)tt * KCB);
    float thr = fdec(g_rowmin[tt]) + MARGIN;

    int cnt = 0;
    for (int j = 0; j < 64; j++) {
        int p = j * 32 + lid;          // half2 index; cols 2p, 2p+1
        __half2 h2 = srow[p];
        bool c0 = (__low2float(h2) <= thr);
        bool c1 = (__high2float(h2) <= thr);
        unsigned m0 = __ballot_sync(0xFFFFFFFFu, c0);
        if (c0) {
            int pos = cnt + __popc(m0 & ((1u << lid) - 1u));
            if (pos < 64) lists[wid][pos] = 2 * p;
        }
        cnt += __popc(m0);
        unsigned m1 = __ballot_sync(0xFFFFFFFFu, c1);
        if (c1) {
            int pos = cnt + __popc(m1 & ((1u << lid) - 1u));
            if (pos < 64) lists[wid][pos] = 2 * p + 1;
        }
        cnt += __popc(m1);
    }
    __syncwarp();

    const float* __restrict__ pe = g_bufA + (size_t)tt * DMD;
    float bv = INFINITY; int bk = 0;
    if (cnt <= 64) {
        for (int c = lid; c < cnt; c += 32) {
            int k = lists[wid][c];
            const float* gr = g_G + (size_t)k * DMD;
            float acc = 0.f;
            #pragma unroll 1
            for (int q = 0; q < DMD; q++) acc = fmaf(pe[q], gr[q], acc);
            float s = g_c0[k] - acc;
            if (s < bv || (s == bv && k < bk)) { bv = s; bk = k; }
        }
    } else {
        for (int k = lid; k < KCB; k += 32) {
            const float* gr = g_G + (size_t)k * DMD;
            float acc = 0.f;
            #pragma unroll 1
            for (int q = 0; q < DMD; q++) acc = fmaf(pe[q], gr[q], acc);
            float s = g_c0[k] - acc;
            if (s < bv || (s == bv && k < bk)) { bv = s; bk = k; }
        }
    }
    for (int o = 16; o; o >>= 1) {
        float ov = __shfl_xor_sync(0xFFFFFFFFu, bv, o);
        int ok = __shfl_xor_sync(0xFFFFFFFFu, bk, o);
        if (ov < bv || (ov == bv && ok < bk)) { bv = ov; bk = ok; }
    }
    if (lid == 0) g_idx[tt] = bk;
}

// ---------------------------------------------------------------------------
__global__ __launch_bounds__(256) void k_gather(const float* __restrict__ outp_b,
                                                float* __restrict__ out) {
    int i = blockIdx.x * 256 + threadIdx.x;
    if (i >= PETOT) return;
    int tkn = i / DMD, d = i % DMD;
    out[i] = g_cout[(size_t)g_idx[tkn] * DMD + d] + outp_b[d];
}

// ---------------------------------------------------------------------------
extern "C" void kernel_launch(void* const* d_in, const int* in_sizes, int n_in,
                              void* d_out, int out_size) {
    const float* x      = (const float*)d_in[0];
    const float* c1w    = (const float*)d_in[1];
    const float* c1b    = (const float*)d_in[2];
    const float* gn1s   = (const float*)d_in[3];
    const float* gn1b   = (const float*)d_in[4];
    const float* c2w    = (const float*)d_in[5];
    const float* c2b    = (const float*)d_in[6];
    const float* gn2s   = (const float*)d_in[7];
    const float* gn2b   = (const float*)d_in[8];
    const float* c3w    = (const float*)d_in[9];
    const float* c3b    = (const float*)d_in[10];
    const float* gn3s   = (const float*)d_in[11];
    const float* gn3b   = (const float*)d_in[12];
    const float* spec_w = (const float*)d_in[13];
    const float* spec_b = (const float*)d_in[14];
    const float* pos_w  = (const float*)d_in[15];
    const float* pos_b  = (const float*)d_in[16];
    const float* inp_w  = (const float*)d_in[17];
    const float* inp_b  = (const float*)d_in[18];
    const float* cb     = (const float*)d_in[19];
    const float* outp_w = (const float*)d_in[20];
    const float* outp_b = (const float*)d_in[21];
    float* out = (float*)d_out;

    static cudaStream_t s2 = nullptr, s3 = nullptr;
    static cudaEvent_t evFork = nullptr, evJoin = nullptr, evDft = nullptr;
    if (s2 == nullptr) {
        cudaStreamCreateWithFlags(&s2, cudaStreamNonBlocking);
        cudaStreamCreateWithFlags(&s3, cudaStreamNonBlocking);
        cudaEventCreateWithFlags(&evFork, cudaEventDisableTiming);
        cudaEventCreateWithFlags(&evJoin, cudaEventDisableTiming);
        cudaEventCreateWithFlags(&evDft,  cudaEventDisableTiming);
    }

    float *pSpec, *pBufA, *pBufB, *pPe;
    cudaGetSymbolAddress((void**)&pSpec, g_spec);
    cudaGetSymbolAddress((void**)&pBufA, g_bufA);
    cudaGetSymbolAddress((void**)&pBufB, g_bufB);
    cudaGetSymbolAddress((void**)&pPe,   g_pe);

    const int EW = (HTOT + 255) / 256;

    // ---- fork ----
    cudaEventRecord(evFork, 0);
    cudaStreamWaitEvent(s2, evFork, 0);
    cudaStreamWaitEvent(s3, evFork, 0);

    // s2: codebook branch
    k_prep<<<dim3(4, 64), 256, 0, s2>>>(cb, inp_w, outp_w);
    k_c0<<<KCB, 256, 0, s2>>>(cb, inp_b);
    k_cvtB<<<(KCB * KPAD + 255) / 256, 256, 0, s2>>>();

    // s3: spectral DFT (only needs x)
    k_dft<<<TT / 2, 256, 0, s3>>>(x);
    cudaEventRecord(evDft, s3);

    // main: conv chain
    k_initmin<<<(TT + 255) / 256, 256>>>();
    k_conv1<<<TT, 256>>>(x, c1w, c1b);
    k_gnstats<<<BB * 5, 256>>>(pBufA);
    k_conv3x<<<BB * 72, 256>>>(pBufA, c2w, c2b, gn1s, gn1b, pBufB);
    k_gnstats<<<BB * 5, 256>>>(pBufB);
    k_conv3x<<<BB * 72, 256>>>(pBufB, c3w, c3b, gn2s, gn2b, pBufA);
    k_gnstats<<<BB * 5, 256>>>(pBufA);
    k_mkpe<<<EW, 256>>>(gn3s, gn3b, spec_b);
    cudaStreamWaitEvent(0, evDft, 0);
    k_sgemm<<<dim3((DMD + 63) / 64, TT / 64), 256>>>(pSpec, spec_w, pPe,
        TT, DMD, NFREQ, NFREQ, 1, NFREQ, DMD, 1);
    k_pos<<<BB * DMD, 256>>>(pos_w, pos_b);
    k_cvtA<<<(int)(((size_t)TTP * KPAD + 255) / 256), 256>>>();

    // ---- join with s2 ----
    cudaEventRecord(evJoin, s2);
    cudaStreamWaitEvent(0, evJoin, 0);

    k_phase1<<<dim3(TTP / 128, KCB / 128), 256>>>();
    k_select<<<(TT + 7) / 8, 256>>>();
    k_gather<<<EW, 256>>>(outp_b, out);
}

// round 10
// speedup vs baseline: 2.3684x; 1.1483x over previous
#include <cuda_runtime.h>
#include <cuda_bf16.h>
#include <cuda_fp16.h>
#include <math.h>
#include <cstdint>

// ---------------------------------------------------------------------------
// CSBrainLLMVQ. Exact fp32 path for everything feeding the output.
//   score[t,k] = 0.5*||cb_k||^2 - inp_b.cb_k - pe2[t].G[k],  G = cb @ inp_w
//   out[t]     = code_out[idx[t]] + outp_b,   code_out = cb @ outp_w.T
// VQ argmin:
//   phase1: mma.sync bf16 2-split -> approx scores (fp16) + rowmin atomics
//   phase2: single-pass candidates within MARGIN, exact fp32 sequential
//           rescore (R3-bit-identical chain) -> exact idx.
// R10: DFT recast as two GEMMs over a bit-identical twiddle TABLE
//      (ctab[n,f] = cosf(2pi*((n*f)%200)/200) == old twc[m]) with the same
//      sequential ascending-n FFMA chain -> g_spec bit-identical, ~210us
//      less device work than the conflict-bound smem-gather k_dft.
// ---------------------------------------------------------------------------

#define BB   32
#define CHN  19
#define NPP  30
#define PSZ  200
#define RR   570
#define TT   18240
#define TTP  18304            // 143*128
#define DMD  200
#define LLM  4096
#define KCB  4096
#define C25  25
#define W8   8
#define HTOT (BB*C25*RR*W8)
#define PETOT (TT*DMD)
#define NFREQ 101
#define KPAD 640
#define MARGIN 4e-3f

__device__ float g_bufA[HTOT];
__device__ float g_bufB[HTOT];
__device__ float g_pe[PETOT];
__device__ float g_spec[TT*NFREQ];
__device__ float g_re[TT*NFREQ];
__device__ float g_im[TT*NFREQ];
__device__ float g_ctab[PSZ*NFREQ];
__device__ float g_stab[PSZ*NFREQ];
__device__ float g_G[KCB*DMD];
__device__ float g_c0[KCB];
__device__ float g_cout[KCB*DMD];
__device__ int   g_idx[TT];
__device__ float g_mean[BB*5];
__device__ float g_rstd[BB*5];
__device__ __nv_bfloat16 g_A2[(size_t)TTP*KPAD];
__device__ __nv_bfloat16 g_B2[(size_t)KCB*KPAD];
__device__ __half g_sap16[(size_t)TTP*KCB];
__device__ unsigned g_rowmin[TT];

__device__ __forceinline__ float gelu_exact(float v) {
    return 0.5f * v * (1.0f + erff(v * 0.70710678118654752f));
}

// order-preserving float <-> uint encode (for unsigned atomicMin)
__device__ __forceinline__ unsigned fenc(float f) {
    unsigned u = __float_as_uint(f);
    return (u & 0x80000000u) ? ~u : (u | 0x80000000u);
}
__device__ __forceinline__ float fdec(unsigned u) {
    unsigned b = (u & 0x80000000u) ? (u & 0x7FFFFFFFu) : ~u;
    return __uint_as_float(b);
}

#define PACKDUP(dst, a) \
    asm("mov.b64 %0, {%1, %1};" : "=l"(dst) : "r"(__float_as_uint(a)))
#define PACK2(dst, a, b) \
    asm("mov.b64 %0, {%1, %2};" : "=l"(dst) : "r"(__float_as_uint(a)), "r"(__float_as_uint(b)))
#define FMA2(acc, a, b) \
    asm("fma.rn.f32x2 %0, %1, %2, %0;" : "+l"(acc) : "l"(a), "l"(b))
#define UNPK2(lo, hi, v) \
    asm("mov.b64 {%0, %1}, %2;" : "=r"(lo), "=r"(hi) : "l"(v))

// ---------------------------------------------------------------------------
__global__ __launch_bounds__(256) void k_initmin() {
    int i = blockIdx.x * 256 + threadIdx.x;
    if (i < TT) g_rowmin[i] = 0xFFFFFFFFu;
}

// ---------------------------------------------------------------------------
// twiddle tables: ctab[n*NFREQ+f] = cosf(ang(m)), m=(n*f)%200 — bit-identical
// to the old twc[m]/tws[m] values (same float expression, same inputs).
// ---------------------------------------------------------------------------
__global__ __launch_bounds__(256) void k_twtab() {
    int i = blockIdx.x * 256 + threadIdx.x;
    if (i >= PSZ * NFREQ) return;
    int n = i / NFREQ, f = i % NFREQ;
    int m = (n * f) % PSZ;
    float ang = 6.283185307179586f * (float)m / 200.f;
    g_ctab[i] = cosf(ang);
    g_stab[i] = sinf(ang);
}

// magnitude epilogue (verbatim expression from the old k_dft)
__global__ __launch_bounds__(256) void k_mag() {
    int i = blockIdx.x * 256 + threadIdx.x;
    if (i >= TT * NFREQ) return;
    float re = g_re[i], im = g_im[i];
    g_spec[i] = sqrtf(re * re + im * im) * 0.005f;
}

// ---------------------------------------------------------------------------
// conv1 (branch-free via zero-padded smem; bit-identical: fma(0,w,acc)=acc)
// ---------------------------------------------------------------------------
__global__ __launch_bounds__(256) void k_conv1(const float* __restrict__ x,
                                               const float* __restrict__ w,
                                               const float* __restrict__ bias) {
    int br = blockIdx.x;
    int b = br / RR, r = br % RR;
    __shared__ float xs[248];          // 24 pad + 200 + 24 pad
    __shared__ float ws[C25 * 49];
    __shared__ float bs[C25];
    int t = threadIdx.x;
    if (t < 248) xs[t] = (t >= 24 && t < 224) ? x[(size_t)br * PSZ + t - 24] : 0.f;
    for (int i = t; i < C25 * 49; i += 256) ws[i] = w[i];
    if (t < C25) bs[t] = bias[t];
    __syncthreads();
    if (t < 200) {
        int oc = t >> 3, ow = t & 7;
        float acc = bs[oc];
        int base = ow * 25;            // padded index
        #pragma unroll 7
        for (int k = 0; k < 49; k++)
            acc += xs[base + k] * ws[oc * 49 + k];
        g_bufA[(((size_t)b * C25 + oc) * RR + r) * W8 + ow] = acc;
    }
}

// ---------------------------------------------------------------------------
__global__ __launch_bounds__(256) void k_gnstats(const float* __restrict__ h) {
    int bg = blockIdx.x;
    int b = bg / 5, g = bg % 5;
    float s1 = 0.f, s2 = 0.f;
    const int per = RR * W8;
    for (int i = threadIdx.x; i < 5 * per; i += 256) {
        int oc = g * 5 + i / per;
        int rw = i % per;
        float v = h[(size_t)(b * C25 + oc) * per + rw];
        s1 += v; s2 += v * v;
    }
    __shared__ float r1[256], r2[256];
    int t = threadIdx.x;
    r1[t] = s1; r2[t] = s2;
    __syncthreads();
    for (int s = 128; s > 0; s >>= 1) {
        if (t < s) { r1[t] += r1[t + s]; r2[t] += r2[t + s]; }
        __syncthreads();
    }
    if (t == 0) {
        float m = r1[0] / 22800.f;
        float var = r2[0] / 22800.f - m * m;
        g_mean[bg] = m;
        g_rstd[bg] = rsqrtf(var + 1e-5f);
    }
}

// ---------------------------------------------------------------------------
__global__ __launch_bounds__(256) void k_conv3x(const float* __restrict__ in,
                                                const float* __restrict__ w,
                                                const float* __restrict__ bias,
                                                const float* __restrict__ gns,
                                                const float* __restrict__ gnb,
                                                float* __restrict__ out) {
    int bi = blockIdx.x;
    int b = bi / 72, rt = bi % 72;
    int r0 = rt * 8;
    int nrows = min(8, RR - r0);
    __shared__ float sIn[C25][8][W8];
    __shared__ float sW[C25 * C25 * 3];
    __shared__ float sB[C25];
    __shared__ float sMean[C25], sRstd[C25], sSc[C25], sBi[C25];
    int t = threadIdx.x;
    for (int i = t; i < C25 * C25 * 3; i += 256) sW[i] = w[i];
    if (t < C25) {
        sB[t] = bias[t];
        int bg = b * 5 + t / 5;
        sMean[t] = g_mean[bg];
        sRstd[t] = g_rstd[bg];
        sSc[t]   = gns[t];
        sBi[t]   = gnb[t];
    }
    for (int i = t; i < C25 * nrows * W8; i += 256) {
        int ic = i / (nrows * W8);
        int lr = (i / W8) % nrows;
        int ww = i & 7;
        sIn[ic][lr][ww] = in[(((size_t)b * C25 + ic) * RR + r0 + lr) * W8 + ww];
    }
    __syncthreads();
    for (int i = t; i < C25 * nrows * W8; i += 256) {
        int ic = i / (nrows * W8);
        int lr = (i / W8) % nrows;
        int ww = i & 7;
        float v = (sIn[ic][lr][ww] - sMean[ic]) * sRstd[ic] * sSc[ic] + sBi[ic];
        sIn[ic][lr][ww] = gelu_exact(v);
    }
    __syncthreads();
    if (t < 200) {
        int oc = t >> 3, ww = t & 7;
        for (int lr = 0; lr < nrows; lr++) {
            float acc = sB[oc];
            #pragma unroll
            for (int ic = 0; ic < C25; ic++) {
                const float* wp = &sW[(oc * C25 + ic) * 3];
                if (ww > 0) acc += sIn[ic][lr][ww - 1] * wp[0];
                acc += sIn[ic][lr][ww] * wp[1];
                if (ww < 7) acc += sIn[ic][lr][ww + 1] * wp[2];
            }
            out[(((size_t)b * C25 + oc) * RR + r0 + lr) * W8 + ww] = acc;
        }
    }
}

// ---------------------------------------------------------------------------
__global__ __launch_bounds__(256) void k_mkpe(const float* __restrict__ gns,
                                              const float* __restrict__ gnb,
                                              const float* __restrict__ spec_b) {
    int i = blockIdx.x * 256 + threadIdx.x;
    if (i >= PETOT) return;
    int tkn = i / DMD, d = i % DMD;
    int b = tkn / RR, r = tkn % RR;
    int ic = d >> 3;
    int bg = b * 5 + ic / 5;
    float raw = g_bufA[(((size_t)b * C25 + ic) * RR + r) * W8 + (d & 7)];
    float v = (raw - g_mean[bg]) * g_rstd[bg] * gns[ic] + gnb[ic];
    g_pe[i] = gelu_exact(v) + spec_b[d];
}

// ---------------------------------------------------------------------------
// generic fp32 SGEMM: C (+)= A @ B, sequential ascending-k FFMA chain.
// ---------------------------------------------------------------------------
__global__ __launch_bounds__(256) void k_sgemm(const float* __restrict__ A,
                                               const float* __restrict__ Bm,
                                               float* __restrict__ C,
                                               int M, int N, int K,
                                               int lda, int bk, int bn, int ldc,
                                               int accFlag) {
    __shared__ __align__(16) float As[8][68];
    __shared__ __align__(16) float Bs[8][68];
    int m0 = blockIdx.y * 64, n0 = blockIdx.x * 64;
    int t = threadIdx.x;
    int tx = t % 16, ty = t / 16;
    float acc[4][4];
    #pragma unroll
    for (int i = 0; i < 4; i++)
        #pragma unroll
        for (int j = 0; j < 4; j++) acc[i][j] = 0.f;

    int nk = (K + 7) / 8;
    for (int kb = 0; kb < nk; kb++) {
        int k0 = kb * 8;
        {
            int kk = t & 7, mm = t >> 3;
            int k = k0 + kk;
            #pragma unroll
            for (int hh = 0; hh < 2; hh++) {
                int m = m0 + mm + hh * 32;
                As[kk][mm + hh * 32] = (k < K && m < M) ? A[(size_t)m * lda + k] : 0.f;
            }
        }
        {
            int kk = t & 7, nn = t >> 3;
            int k = k0 + kk;
            #pragma unroll
            for (int hh = 0; hh < 2; hh++) {
                int n = n0 + nn + hh * 32;
                Bs[kk][nn + hh * 32] = (k < K && n < N) ? Bm[(size_t)k * bk + (size_t)n * bn] : 0.f;
            }
        }
        __syncthreads();
        #pragma unroll
        for (int kk = 0; kk < 8; kk++) {
            float4 av = *reinterpret_cast<const float4*>(&As[kk][ty * 4]);
            float4 bv = *reinterpret_cast<const float4*>(&Bs[kk][tx * 4]);
            float a[4] = {av.x, av.y, av.z, av.w};
            float bb[4] = {bv.x, bv.y, bv.z, bv.w};
            #pragma unroll
            for (int i = 0; i < 4; i++)
                #pragma unroll
                for (int j = 0; j < 4; j++) acc[i][j] += a[i] * bb[j];
        }
        __syncthreads();
    }
    #pragma unroll
    for (int i = 0; i < 4; i++) {
        int m = m0 + ty * 4 + i;
        if (m >= M) continue;
        #pragma unroll
        for (int j = 0; j < 4; j++) {
            int n = n0 + tx * 4 + j;
            if (n < N) {
                size_t o = (size_t)m * ldc + n;
                C[o] = accFlag ? (C[o] + acc[i][j]) : acc[i][j];
            }
        }
    }
}

// ---------------------------------------------------------------------------
__global__ __launch_bounds__(256) void k_c0(const float* __restrict__ cb,
                                            const float* __restrict__ inp_b) {
    int k = blockIdx.x;
    float s = 0.f, sb = 0.f;
    for (int l = threadIdx.x; l < LLM; l += 256) {
        float v = cb[(size_t)k * LLM + l];
        s += v * v;
        sb += inp_b[l] * v;
    }
    __shared__ float r1[256], r2[256];
    int t = threadIdx.x;
    r1[t] = s; r2[t] = sb;
    __syncthreads();
    for (int st = 128; st > 0; st >>= 1) {
        if (t < st) { r1[t] += r1[t + st]; r2[t] += r2[t + st]; }
        __syncthreads();
    }
    if (t == 0) g_c0[k] = 0.5f * r1[0] - r2[0];
}

// ---------------------------------------------------------------------------
// k_prep (R3-identical): dual GEMM sharing A-tile (cb); FMA2 + reg packing.
// ---------------------------------------------------------------------------
__global__ __launch_bounds__(256) void k_prep(const float* __restrict__ cb,
                                              const float* __restrict__ inp_w,
                                              const float* __restrict__ outp_w) {
    __shared__ __align__(16) float As[2][8][68];
    __shared__ __align__(16) float B1s[2][8][68];
    __shared__ __align__(16) float B2s[2][8][68];
    const int t = threadIdx.x;
    const int tx = t & 15, ty = t >> 4;
    const int lk = t & 7, lm = t >> 3;
    const int nn = t & 63, kq = t >> 6;
    const int m0 = blockIdx.y * 64, n0 = blockIdx.x * 64;

    unsigned long long a1[4][2], a2[4][2];
    #pragma unroll
    for (int i = 0; i < 4; i++)
        #pragma unroll
        for (int jp = 0; jp < 2; jp++) { a1[i][jp] = 0ULL; a2[i][jp] = 0ULL; }

    #pragma unroll
    for (int h = 0; h < 2; h++) {
        As[0][lk][lm + h * 32] = cb[(size_t)(m0 + lm + h * 32) * LLM + lk];
        int kk = kq + h * 4;
        B1s[0][kk][nn] = (n0 + nn < DMD) ? inp_w[(size_t)kk * DMD + n0 + nn] : 0.f;
        B2s[0][lk][lm + h * 32] = (n0 + lm + h * 32 < DMD)
            ? outp_w[(size_t)(n0 + lm + h * 32) * LLM + lk] : 0.f;
    }
    __syncthreads();
    for (int kb = 0; kb < LLM / 8; kb++) {
        int cur = kb & 1, nxt = cur ^ 1;
        if (kb < LLM / 8 - 1) {
            int k0 = (kb + 1) * 8;
            #pragma unroll
            for (int h = 0; h < 2; h++) {
                As[nxt][lk][lm + h * 32] = cb[(size_t)(m0 + lm + h * 32) * LLM + k0 + lk];
                int kk = kq + h * 4;
                B1s[nxt][kk][nn] = (n0 + nn < DMD) ? inp_w[(size_t)(k0 + kk) * DMD + n0 + nn] : 0.f;
                B2s[nxt][lk][lm + h * 32] = (n0 + lm + h * 32 < DMD)
                    ? outp_w[(size_t)(n0 + lm + h * 32) * LLM + k0 + lk] : 0.f;
            }
        }
        #pragma unroll
        for (int kk = 0; kk < 8; kk++) {
            float4 av = *reinterpret_cast<const float4*>(&As[cur][kk][ty * 4]);
            float4 b1 = *reinterpret_cast<const float4*>(&B1s[cur][kk][tx * 4]);
            float4 b2 = *reinterpret_cast<const float4*>(&B2s[cur][kk][tx * 4]);
            unsigned long long b1p[2], b2p[2];
            PACK2(b1p[0], b1.x, b1.y); PACK2(b1p[1], b1.z, b1.w);
            PACK2(b2p[0], b2.x, b2.y); PACK2(b2p[1], b2.z, b2.w);
            float aa[4] = {av.x, av.y, av.z, av.w};
            #pragma unroll
            for (int i = 0; i < 4; i++) {
                unsigned long long ap;
                PACKDUP(ap, aa[i]);
                FMA2(a1[i][0], ap, b1p[0]);
                FMA2(a1[i][1], ap, b1p[1]);
                FMA2(a2[i][0], ap, b2p[0]);
                FMA2(a2[i][1], ap, b2p[1]);
            }
        }
        __syncthreads();
    }
    #pragma unroll
    for (int i = 0; i < 4; i++) {
        int m = m0 + ty * 4 + i;
        #pragma unroll
        for (int jp = 0; jp < 2; jp++) {
            unsigned lo, hi;
            int n = n0 + tx * 4 + jp * 2;
            UNPK2(lo, hi, a1[i][jp]);
            if (n < DMD)     g_G[(size_t)m * DMD + n]     = __uint_as_float(lo);
            if (n + 1 < DMD) g_G[(size_t)m * DMD + n + 1] = __uint_as_float(hi);
            UNPK2(lo, hi, a2[i][jp]);
            if (n < DMD)     g_cout[(size_t)m * DMD + n]     = __uint_as_float(lo);
            if (n + 1 < DMD) g_cout[(size_t)m * DMD + n + 1] = __uint_as_float(hi);
        }
    }
}

// ---------------------------------------------------------------------------
__global__ __launch_bounds__(256) void k_pos(const float* __restrict__ pw,
                                             const float* __restrict__ pb) {
    int b = blockIdx.x / DMD, d = blockIdx.x % DMD;
    __shared__ float mp[RR];
    __shared__ float w[133];
    int t = threadIdx.x;
    for (int i = t; i < RR; i += 256)
        mp[i] = g_pe[((size_t)b * RR + i) * DMD + d];
    if (t < 133) w[t] = pw[d * 133 + t];
    __syncthreads();
    float bias = pb[d];
    for (int o = t; o < RR; o += 256) {
        int ch = o / NPP, pn = o % NPP;
        float acc = mp[o] + bias;
        #pragma unroll
        for (int i = 0; i < 19; i++) {
            int ci = ch + i - 9;
            if (ci < 0 || ci >= CHN) continue;
            int base = ci * NPP;
            #pragma unroll
            for (int j = 0; j < 7; j++) {
                int pj = pn + j - 3;
                if (pj < 0 || pj >= NPP) continue;
                acc += mp[base + pj] * w[i * 7 + j];
            }
        }
        g_bufA[((size_t)b * RR + o) * DMD + d] = acc;
    }
}

// ---------------------------------------------------------------------------
// bf16 2-split conversion: A' = [P_hi | P_hi | P_lo], B' = [G_hi | G_lo | G_hi]
// ---------------------------------------------------------------------------
__global__ __launch_bounds__(256) void k_cvtA() {
    size_t i = (size_t)blockIdx.x * 256 + threadIdx.x;
    if (i >= (size_t)TTP * KPAD) return;
    int t = (int)(i / KPAD), c = (int)(i % KPAD);
    __nv_bfloat16 v = __float2bfloat16(0.f);
    if (t < TT && c < 600) {
        int d = (c < 200) ? c : (c < 400 ? c - 200 : c - 400);
        float x = g_bufA[(size_t)t * DMD + d];
        __nv_bfloat16 h = __float2bfloat16(x);
        if (c < 400) v = h;
        else         v = __float2bfloat16(x - __bfloat162float(h));
    }
    g_A2[i] = v;
}

__global__ __launch_bounds__(256) void k_cvtB() {
    size_t i = (size_t)blockIdx.x * 256 + threadIdx.x;
    if (i >= (size_t)KCB * KPAD) return;
    int k = (int)(i / KPAD), c = (int)(i % KPAD);
    __nv_bfloat16 v = __float2bfloat16(0.f);
    if (c < 600) {
        int d = (c < 200) ? c : (c < 400 ? c - 200 : c - 400);
        float x = g_G[(size_t)k * DMD + d];
        __nv_bfloat16 h = __float2bfloat16(x);
        if (c < 200 || c >= 400) v = h;
        else v = __float2bfloat16(x - __bfloat162float(h));
    }
    g_B2[i] = v;
}

// ---------------------------------------------------------------------------
// phase1: approx scores via mma.sync m16n8k16 bf16->fp32, register-prefetch
// pipeline, fp16 score store + per-row encoded atomicMin into g_rowmin.
// ---------------------------------------------------------------------------
#define SK 72

__device__ __forceinline__ void mma_bf16(float* c, uint32_t a0, uint32_t a1,
                                         uint32_t a2, uint32_t a3,
                                         uint32_t b0, uint32_t b1) {
    asm volatile(
        "mma.sync.aligned.m16n8k16.row.col.f32.bf16.bf16.f32 "
        "{%0,%1,%2,%3}, {%4,%5,%6,%7}, {%8,%9}, {%0,%1,%2,%3};"
        : "+f"(c[0]), "+f"(c[1]), "+f"(c[2]), "+f"(c[3])
        : "r"(a0), "r"(a1), "r"(a2), "r"(a3), "r"(b0), "r"(b1));
}

__global__ __launch_bounds__(256) void k_phase1() {
    __shared__ __nv_bfloat16 As[128][SK];
    __shared__ __nv_bfloat16 Bs[128][SK];
    __shared__ unsigned urmin[128];
    const int t = threadIdx.x, wid = t >> 5, lane = t & 31;
    const int m0 = blockIdx.x * 128, n0 = blockIdx.y * 128;
    const int wm = wid >> 2, wn = wid & 3;
    const int r = lane >> 2, cc = (lane & 3) * 2;
    const int lrow = t >> 3, lq = t & 7;

    if (t < 128) urmin[t] = 0xFFFFFFFFu;

    float acc[4][4][4];
    #pragma unroll
    for (int mt = 0; mt < 4; mt++)
        #pragma unroll
        for (int nt = 0; nt < 4; nt++)
            #pragma unroll
            for (int q = 0; q < 4; q++) acc[mt][nt][q] = 0.f;

    float4 pa[4], pb[4];
    #pragma unroll
    for (int s = 0; s < 4; s++) {
        int row = lrow + s * 32;
        pa[s] = *reinterpret_cast<const float4*>(g_A2 + (size_t)(m0 + row) * KPAD + lq * 8);
        pb[s] = *reinterpret_cast<const float4*>(g_B2 + (size_t)(n0 + row) * KPAD + lq * 8);
    }

    for (int ch = 0; ch < 10; ch++) {
        #pragma unroll
        for (int s = 0; s < 4; s++) {
            int row = lrow + s * 32;
            *reinterpret_cast<float4*>(&As[row][lq * 8]) = pa[s];
            *reinterpret_cast<float4*>(&Bs[row][lq * 8]) = pb[s];
        }
        __syncthreads();
        if (ch < 9) {
            #pragma unroll
            for (int s = 0; s < 4; s++) {
                int row = lrow + s * 32;
                pa[s] = *reinterpret_cast<const float4*>(
                    g_A2 + (size_t)(m0 + row) * KPAD + (ch + 1) * 64 + lq * 8);
                pb[s] = *reinterpret_cast<const float4*>(
                    g_B2 + (size_t)(n0 + row) * KPAD + (ch + 1) * 64 + lq * 8);
            }
        }
        #pragma unroll
        for (int ks = 0; ks < 4; ks++) {
            const int k0 = ks * 16;
            uint32_t a[4][4], b[4][2];
            #pragma unroll
            for (int mt = 0; mt < 4; mt++) {
                int rowA = wm * 64 + mt * 16 + r;
                a[mt][0] = *reinterpret_cast<const uint32_t*>(&As[rowA][k0 + cc]);
                a[mt][1] = *reinterpret_cast<const uint32_t*>(&As[rowA + 8][k0 + cc]);
                a[mt][2] = *reinterpret_cast<const uint32_t*>(&As[rowA][k0 + cc + 8]);
                a[mt][3] = *reinterpret_cast<const uint32_t*>(&As[rowA + 8][k0 + cc + 8]);
            }
            #pragma unroll
            for (int nt = 0; nt < 4; nt++) {
                int rowB = wn * 32 + nt * 8 + r;
                b[nt][0] = *reinterpret_cast<const uint32_t*>(&Bs[rowB][k0 + cc]);
                b[nt][1] = *reinterpret_cast<const uint32_t*>(&Bs[rowB][k0 + cc + 8]);
            }
            #pragma unroll
            for (int mt = 0; mt < 4; mt++)
                #pragma unroll
                for (int nt = 0; nt < 4; nt++)
                    mma_bf16(acc[mt][nt], a[mt][0], a[mt][1], a[mt][2], a[mt][3],
                             b[nt][0], b[nt][1]);
        }
        __syncthreads();
    }

    #pragma unroll
    for (int mt = 0; mt < 4; mt++) {
        int lr0 = wm * 64 + mt * 16 + r;
        float mlo = INFINITY, mhi = INFINITY;
        #pragma unroll
        for (int nt = 0; nt < 4; nt++) {
            int col = n0 + wn * 32 + nt * 8 + cc;
            float c0a = g_c0[col], c0b = g_c0[col + 1];
            float s0 = c0a - acc[mt][nt][0], s1 = c0b - acc[mt][nt][1];
            float s2 = c0a - acc[mt][nt][2], s3 = c0b - acc[mt][nt][3];
            mlo = fminf(mlo, fminf(s0, s1));
            mhi = fminf(mhi, fminf(s2, s3));
            int row0 = m0 + lr0;
            if (row0 < TT)
                *reinterpret_cast<__half2*>(&g_sap16[(size_t)row0 * KCB + col]) =
                    __floats2half2_rn(s0, s1);
            if (row0 + 8 < TT)
                *reinterpret_cast<__half2*>(&g_sap16[(size_t)(row0 + 8) * KCB + col]) =
                    __floats2half2_rn(s2, s3);
        }
        atomicMin(&urmin[lr0], fenc(mlo));
        atomicMin(&urmin[lr0 + 8], fenc(mhi));
    }
    __syncthreads();
    if (t < 128 && m0 + t < TT)
        atomicMin(&g_rowmin[m0 + t], urmin[t]);
}

// ---------------------------------------------------------------------------
// phase2: per-token (one warp): thr from g_rowmin, single candidate pass
// over fp16 scores, EXACT fp32 sequential rescore -> first-min idx.
// ---------------------------------------------------------------------------
__global__ __launch_bounds__(256) void k_select() {
    __shared__ int lists[8][64];
    int wid = threadIdx.x >> 5, lid = threadIdx.x & 31;
    int tt = blockIdx.x * 8 + wid;
    if (tt >= TT) return;
    const __half2* __restrict__ srow =
        reinterpret_cast<const __half2*>(g_sap16 + (size_t)tt * KCB);
    float thr = fdec(g_rowmin[tt]) + MARGIN;

    int cnt = 0;
    for (int j = 0; j < 64; j++) {
        int p = j * 32 + lid;
        __half2 h2 = srow[p];
        bool c0 = (__low2float(h2) <= thr);
        bool c1 = (__high2float(h2) <= thr);
        unsigned m0 = __ballot_sync(0xFFFFFFFFu, c0);
        if (c0) {
            int pos = cnt + __popc(m0 & ((1u << lid) - 1u));
            if (pos < 64) lists[wid][pos] = 2 * p;
        }
        cnt += __popc(m0);
        unsigned m1 = __ballot_sync(0xFFFFFFFFu, c1);
        if (c1) {
            int pos = cnt + __popc(m1 & ((1u << lid) - 1u));
            if (pos < 64) lists[wid][pos] = 2 * p + 1;
        }
        cnt += __popc(m1);
    }
    __syncwarp();

    const float* __restrict__ pe = g_bufA + (size_t)tt * DMD;
    float bv = INFINITY; int bk = 0;
    if (cnt <= 64) {
        for (int c = lid; c < cnt; c += 32) {
            int k = lists[wid][c];
            const float* gr = g_G + (size_t)k * DMD;
            float acc = 0.f;
            #pragma unroll 1
            for (int q = 0; q < DMD; q++) acc = fmaf(pe[q], gr[q], acc);
            float s = g_c0[k] - acc;
            if (s < bv || (s == bv && k < bk)) { bv = s; bk = k; }
        }
    } else {
        for (int k = lid; k < KCB; k += 32) {
            const float* gr = g_G + (size_t)k * DMD;
            float acc = 0.f;
            #pragma unroll 1
            for (int q = 0; q < DMD; q++) acc = fmaf(pe[q], gr[q], acc);
            float s = g_c0[k] - acc;
            if (s < bv || (s == bv && k < bk)) { bv = s; bk = k; }
        }
    }
    for (int o = 16; o; o >>= 1) {
        float ov = __shfl_xor_sync(0xFFFFFFFFu, bv, o);
        int ok = __shfl_xor_sync(0xFFFFFFFFu, bk, o);
        if (ov < bv || (ov == bv && ok < bk)) { bv = ov; bk = ok; }
    }
    if (lid == 0) g_idx[tt] = bk;
}

// ---------------------------------------------------------------------------
__global__ __launch_bounds__(256) void k_gather(const float* __restrict__ outp_b,
                                                float* __restrict__ out) {
    int i = blockIdx.x * 256 + threadIdx.x;
    if (i >= PETOT) return;
    int tkn = i / DMD, d = i % DMD;
    out[i] = g_cout[(size_t)g_idx[tkn] * DMD + d] + outp_b[d];
}

// ---------------------------------------------------------------------------
extern "C" void kernel_launch(void* const* d_in, const int* in_sizes, int n_in,
                              void* d_out, int out_size) {
    const float* x      = (const float*)d_in[0];
    const float* c1w    = (const float*)d_in[1];
    const float* c1b    = (const float*)d_in[2];
    const float* gn1s   = (const float*)d_in[3];
    const float* gn1b   = (const float*)d_in[4];
    const float* c2w    = (const float*)d_in[5];
    const float* c2b    = (const float*)d_in[6];
    const float* gn2s   = (const float*)d_in[7];
    const float* gn2b   = (const float*)d_in[8];
    const float* c3w    = (const float*)d_in[9];
    const float* c3b    = (const float*)d_in[10];
    const float* gn3s   = (const float*)d_in[11];
    const float* gn3b   = (const float*)d_in[12];
    const float* spec_w = (const float*)d_in[13];
    const float* spec_b = (const float*)d_in[14];
    const float* pos_w  = (const float*)d_in[15];
    const float* pos_b  = (const float*)d_in[16];
    const float* inp_w  = (const float*)d_in[17];
    const float* inp_b  = (const float*)d_in[18];
    const float* cb     = (const float*)d_in[19];
    const float* outp_w = (const float*)d_in[20];
    const float* outp_b = (const float*)d_in[21];
    float* out = (float*)d_out;

    static cudaStream_t s2 = nullptr, s3 = nullptr;
    static cudaEvent_t evFork = nullptr, evJoin = nullptr, evDft = nullptr;
    if (s2 == nullptr) {
        cudaStreamCreateWithFlags(&s2, cudaStreamNonBlocking);
        cudaStreamCreateWithFlags(&s3, cudaStreamNonBlocking);
        cudaEventCreateWithFlags(&evFork, cudaEventDisableTiming);
        cudaEventCreateWithFlags(&evJoin, cudaEventDisableTiming);
        cudaEventCreateWithFlags(&evDft,  cudaEventDisableTiming);
    }

    float *pSpec, *pBufA, *pBufB, *pPe, *pRe, *pIm, *pCtab, *pStab;
    cudaGetSymbolAddress((void**)&pSpec, g_spec);
    cudaGetSymbolAddress((void**)&pBufA, g_bufA);
    cudaGetSymbolAddress((void**)&pBufB, g_bufB);
    cudaGetSymbolAddress((void**)&pPe,   g_pe);
    cudaGetSymbolAddress((void**)&pRe,   g_re);
    cudaGetSymbolAddress((void**)&pIm,   g_im);
    cudaGetSymbolAddress((void**)&pCtab, g_ctab);
    cudaGetSymbolAddress((void**)&pStab, g_stab);

    const int EW = (HTOT + 255) / 256;

    // ---- fork ----
    cudaEventRecord(evFork, 0);
    cudaStreamWaitEvent(s2, evFork, 0);
    cudaStreamWaitEvent(s3, evFork, 0);

    // s2: codebook branch
    k_prep<<<dim3(4, 64), 256, 0, s2>>>(cb, inp_w, outp_w);
    k_c0<<<KCB, 256, 0, s2>>>(cb, inp_b);
    k_cvtB<<<(KCB * KPAD + 255) / 256, 256, 0, s2>>>();

    // s3: spectral DFT via GEMM (bit-identical twiddle table + same FFMA chain)
    k_twtab<<<(PSZ * NFREQ + 255) / 256, 256, 0, s3>>>();
    k_sgemm<<<dim3((NFREQ + 63) / 64, TT / 64), 256, 0, s3>>>(x, pCtab, pRe,
        TT, NFREQ, PSZ, PSZ, NFREQ, 1, NFREQ, 0);
    k_sgemm<<<dim3((NFREQ + 63) / 64, TT / 64), 256, 0, s3>>>(x, pStab, pIm,
        TT, NFREQ, PSZ, PSZ, NFREQ, 1, NFREQ, 0);
    k_mag<<<(TT * NFREQ + 255) / 256, 256, 0, s3>>>();
    cudaEventRecord(evDft, s3);

    // main: conv chain
    k_initmin<<<(TT + 255) / 256, 256>>>();
    k_conv1<<<TT, 256>>>(x, c1w, c1b);
    k_gnstats<<<BB * 5, 256>>>(pBufA);
    k_conv3x<<<BB * 72, 256>>>(pBufA, c2w, c2b, gn1s, gn1b, pBufB);
    k_gnstats<<<BB * 5, 256>>>(pBufB);
    k_conv3x<<<BB * 72, 256>>>(pBufB, c3w, c3b, gn2s, gn2b, pBufA);
    k_gnstats<<<BB * 5, 256>>>(pBufA);
    k_mkpe<<<EW, 256>>>(gn3s, gn3b, spec_b);
    cudaStreamWaitEvent(0, evDft, 0);
    k_sgemm<<<dim3((DMD + 63) / 64, TT / 64), 256>>>(pSpec, spec_w, pPe,
        TT, DMD, NFREQ, NFREQ, 1, NFREQ, DMD, 1);
    k_pos<<<BB * DMD, 256>>>(pos_w, pos_b);
    k_cvtA<<<(int)(((size_t)TTP * KPAD + 255) / 256), 256>>>();

    // ---- join with s2 ----
    cudaEventRecord(evJoin, s2);
    cudaStreamWaitEvent(0, evJoin, 0);

    k_phase1<<<dim3(TTP / 128, KCB / 128), 256>>>();
    k_select<<<(TT + 7) / 8, 256>>>();
    k_gather<<<EW, 256>>>(outp_b, out);
}